// round 1
// baseline (speedup 1.0000x reference)
#include <cuda_runtime.h>

// Problem constants
#define BB 2
#define TT 2048
#define EE 1024
#define HH 16
#define DHS 64
#define MTOT (BB*TT)          // 4096 rows

// ---------------- scratch (device globals; no allocation) ----------------
__device__ float g_Q[BB*HH*TT*DHS];     // [B,H,T,64]
__device__ float g_K[BB*HH*TT*DHS];
__device__ float g_V[BB*HH*TT*DHS];
__device__ float g_O[MTOT*EE];          // attention output, concat layout [B*T, E]
__device__ float g_t1[MTOT*EE];         // pre-LN buffer
__device__ float g_x1[MTOT*EE];         // post-LN1
__device__ float g_h[MTOT*4*EE];        // FFN hidden [4096, 4096]

// ---------------- QKV GEMM: x[4096,1024] @ W[h,e,d] -> [B,H,T,64] ----------
// grid: (N/128=8, M/128=32, 3), block 256
__global__ __launch_bounds__(256) void gemm_qkv(
    const float* __restrict__ X,
    const float* __restrict__ Wq, const float* __restrict__ Wk,
    const float* __restrict__ Wv)
{
    __shared__ float As[16][128];   // As[k][m]
    __shared__ float Bs[16][128];   // Bs[k][n]
    const float* Ws = (blockIdx.z == 0) ? Wq : (blockIdx.z == 1) ? Wk : Wv;
    float* Ob = (blockIdx.z == 0) ? g_Q : (blockIdx.z == 1) ? g_K : g_V;

    const int tid = threadIdx.x;
    const int bm = blockIdx.y * 128, bn = blockIdx.x * 128;
    const int ty = tid >> 4, tx = tid & 15;
    const int K = 1024, N = 1024;

    const int ar = tid >> 2;          // A row (first half)
    const int ak = (tid & 3) << 2;    // A k-col (float4)
    const int br = tid >> 5;          // B k-row (first half)
    const int bc = (tid & 31) << 2;   // B n-col (float4)

    float acc[8][8] = {};
    for (int k0 = 0; k0 < K; k0 += 16) {
        float4 a0 = *(const float4*)&X[(bm + ar) * K + k0 + ak];
        float4 a1 = *(const float4*)&X[(bm + ar + 64) * K + k0 + ak];
        // Wq layout [H,E,HS]: idx = h*65536 + e*64 + d
        int n = bn + bc;
        int hh = n >> 6, dd = n & 63;
        float4 b0 = *(const float4*)&Ws[hh * 65536 + (k0 + br) * 64 + dd];
        float4 b1 = *(const float4*)&Ws[hh * 65536 + (k0 + br + 8) * 64 + dd];
        __syncthreads();
        As[ak + 0][ar] = a0.x; As[ak + 1][ar] = a0.y;
        As[ak + 2][ar] = a0.z; As[ak + 3][ar] = a0.w;
        As[ak + 0][ar + 64] = a1.x; As[ak + 1][ar + 64] = a1.y;
        As[ak + 2][ar + 64] = a1.z; As[ak + 3][ar + 64] = a1.w;
        *(float4*)&Bs[br][bc]     = b0;
        *(float4*)&Bs[br + 8][bc] = b1;
        __syncthreads();
        #pragma unroll
        for (int k = 0; k < 16; k++) {
            float ra[8], rb[8];
            #pragma unroll
            for (int i = 0; i < 8; i++) ra[i] = As[k][ty * 8 + i];
            #pragma unroll
            for (int j = 0; j < 8; j++) rb[j] = Bs[k][tx * 8 + j];
            #pragma unroll
            for (int i = 0; i < 8; i++)
                #pragma unroll
                for (int j = 0; j < 8; j++) acc[i][j] += ra[i] * rb[j];
        }
    }
    #pragma unroll
    for (int i = 0; i < 8; i++) {
        int m = bm + ty * 8 + i;
        int b = m >> 11, t = m & 2047;
        #pragma unroll
        for (int j = 0; j < 8; j++) {
            int n = bn + tx * 8 + j;
            int hh = n >> 6, dd = n & 63;
            Ob[((b * HH + hh) * TT + t) * DHS + dd] = acc[i][j];
        }
    }
}

// ---------------- generic row-major GEMM with epilogues --------------------
// EPI 0: C = A@B + bias + res   (res width == N)
// EPI 1: C = relu(A@B + bias)
template <int EPI>
__global__ __launch_bounds__(256) void gemm_rm(
    const float* __restrict__ A, const float* __restrict__ Bw,
    const float* __restrict__ bias, const float* __restrict__ res,
    float* __restrict__ C, int M, int N, int K)
{
    __shared__ float As[16][128];
    __shared__ float Bs[16][128];
    const int tid = threadIdx.x;
    const int bm = blockIdx.y * 128, bn = blockIdx.x * 128;
    const int ty = tid >> 4, tx = tid & 15;
    const int ar = tid >> 2, ak = (tid & 3) << 2;
    const int br = tid >> 5, bc = (tid & 31) << 2;

    float acc[8][8] = {};
    for (int k0 = 0; k0 < K; k0 += 16) {
        float4 a0 = *(const float4*)&A[(bm + ar) * K + k0 + ak];
        float4 a1 = *(const float4*)&A[(bm + ar + 64) * K + k0 + ak];
        float4 b0 = *(const float4*)&Bw[(k0 + br) * N + bn + bc];
        float4 b1 = *(const float4*)&Bw[(k0 + br + 8) * N + bn + bc];
        __syncthreads();
        As[ak + 0][ar] = a0.x; As[ak + 1][ar] = a0.y;
        As[ak + 2][ar] = a0.z; As[ak + 3][ar] = a0.w;
        As[ak + 0][ar + 64] = a1.x; As[ak + 1][ar + 64] = a1.y;
        As[ak + 2][ar + 64] = a1.z; As[ak + 3][ar + 64] = a1.w;
        *(float4*)&Bs[br][bc]     = b0;
        *(float4*)&Bs[br + 8][bc] = b1;
        __syncthreads();
        #pragma unroll
        for (int k = 0; k < 16; k++) {
            float ra[8], rb[8];
            #pragma unroll
            for (int i = 0; i < 8; i++) ra[i] = As[k][ty * 8 + i];
            #pragma unroll
            for (int j = 0; j < 8; j++) rb[j] = Bs[k][tx * 8 + j];
            #pragma unroll
            for (int i = 0; i < 8; i++)
                #pragma unroll
                for (int j = 0; j < 8; j++) acc[i][j] += ra[i] * rb[j];
        }
    }
    #pragma unroll
    for (int i = 0; i < 8; i++) {
        int m = bm + ty * 8 + i;
        #pragma unroll
        for (int j = 0; j < 8; j++) {
            int n = bn + tx * 8 + j;
            float v = acc[i][j] + bias[n];
            if (EPI == 0) v += res[m * N + n];
            else          v = fmaxf(v, 0.0f);
            C[m * N + n] = v;
        }
    }
}

// ---------------- fused causal flash attention -----------------------------
// grid (T/64=32, H=16, B=2), block 256, dynamic smem 4*64*65*4 = 66560 B
#define SSTR 65
__global__ __launch_bounds__(256) void attn_kernel(float* __restrict__ Ocat)
{
    extern __shared__ float sm[];
    float* Qs = sm;
    float* Ks = sm + 64 * SSTR;
    float* Vs = sm + 2 * 64 * SSTR;
    float* Ps = sm + 3 * 64 * SSTR;

    const int qt = blockIdx.x, h = blockIdx.y, b = blockIdx.z;
    const int tid = threadIdx.x, ty = tid >> 4, tx = tid & 15;
    const int base = ((b * HH + h) * TT) * DHS;
    const float* Qg = g_Q + base;
    const float* Kg = g_K + base;
    const float* Vg = g_V + base;

    // load Q tile (scaled by 1/sqrt(64) = 0.125)
    #pragma unroll
    for (int i = 0; i < 4; i++) {
        int idx = tid + i * 256;          // float4 unit index 0..1023
        int r = idx >> 4, c = (idx & 15) * 4;
        float4 v = *(const float4*)&Qg[(qt * 64 + r) * 64 + c];
        Qs[r * SSTR + c + 0] = v.x * 0.125f;
        Qs[r * SSTR + c + 1] = v.y * 0.125f;
        Qs[r * SSTR + c + 2] = v.z * 0.125f;
        Qs[r * SSTR + c + 3] = v.w * 0.125f;
    }

    float m_i[4], l_i[4], o[4][4];
    #pragma unroll
    for (int i = 0; i < 4; i++) {
        m_i[i] = -1e30f; l_i[i] = 0.0f;
        #pragma unroll
        for (int j = 0; j < 4; j++) o[i][j] = 0.0f;
    }

    for (int kt = 0; kt <= qt; kt++) {
        __syncthreads();
        #pragma unroll
        for (int i = 0; i < 4; i++) {
            int idx = tid + i * 256;
            int r = idx >> 4, c = (idx & 15) * 4;
            float4 kv = *(const float4*)&Kg[(kt * 64 + r) * 64 + c];
            Ks[r * SSTR + c + 0] = kv.x; Ks[r * SSTR + c + 1] = kv.y;
            Ks[r * SSTR + c + 2] = kv.z; Ks[r * SSTR + c + 3] = kv.w;
            float4 vv = *(const float4*)&Vg[(kt * 64 + r) * 64 + c];
            Vs[r * SSTR + c + 0] = vv.x; Vs[r * SSTR + c + 1] = vv.y;
            Vs[r * SSTR + c + 2] = vv.z; Vs[r * SSTR + c + 3] = vv.w;
        }
        __syncthreads();

        float s[4][4] = {};
        #pragma unroll 8
        for (int k = 0; k < 64; k++) {
            float qv[4], kv[4];
            #pragma unroll
            for (int i = 0; i < 4; i++) qv[i] = Qs[(4 * ty + i) * SSTR + k];
            #pragma unroll
            for (int j = 0; j < 4; j++) kv[j] = Ks[(4 * tx + j) * SSTR + k];
            #pragma unroll
            for (int i = 0; i < 4; i++)
                #pragma unroll
                for (int j = 0; j < 4; j++) s[i][j] += qv[i] * kv[j];
        }
        if (kt == qt) {
            #pragma unroll
            for (int i = 0; i < 4; i++)
                #pragma unroll
                for (int j = 0; j < 4; j++)
                    if (4 * tx + j > 4 * ty + i) s[i][j] = -1e30f;
        }
        // online softmax: rows r = 4*ty+i, reduce over 16 lanes sharing ty
        #pragma unroll
        for (int i = 0; i < 4; i++) {
            float rm = s[i][0];
            #pragma unroll
            for (int j = 1; j < 4; j++) rm = fmaxf(rm, s[i][j]);
            #pragma unroll
            for (int off = 8; off >= 1; off >>= 1)
                rm = fmaxf(rm, __shfl_xor_sync(0xffffffffu, rm, off));
            float mn = fmaxf(m_i[i], rm);
            float alpha = __expf(m_i[i] - mn);
            m_i[i] = mn;
            float rs = 0.0f;
            #pragma unroll
            for (int j = 0; j < 4; j++) {
                s[i][j] = __expf(s[i][j] - mn);
                rs += s[i][j];
            }
            #pragma unroll
            for (int off = 8; off >= 1; off >>= 1)
                rs += __shfl_xor_sync(0xffffffffu, rs, off);
            l_i[i] = l_i[i] * alpha + rs;
            #pragma unroll
            for (int j = 0; j < 4; j++) {
                o[i][j] *= alpha;
                Ps[(4 * ty + i) * SSTR + 4 * tx + j] = s[i][j];
            }
        }
        __syncthreads();
        #pragma unroll 8
        for (int k = 0; k < 64; k++) {
            float pv[4], vv[4];
            #pragma unroll
            for (int i = 0; i < 4; i++) pv[i] = Ps[(4 * ty + i) * SSTR + k];
            #pragma unroll
            for (int j = 0; j < 4; j++) vv[j] = Vs[k * SSTR + 4 * tx + j];
            #pragma unroll
            for (int i = 0; i < 4; i++)
                #pragma unroll
                for (int j = 0; j < 4; j++) o[i][j] += pv[i] * vv[j];
        }
    }
    // write concat layout: Ocat[(b*T + t)*E + h*64 + c]
    #pragma unroll
    for (int i = 0; i < 4; i++) {
        int t = qt * 64 + 4 * ty + i;
        float inv = 1.0f / l_i[i];
        #pragma unroll
        for (int j = 0; j < 4; j++) {
            int c = 4 * tx + j;
            Ocat[(b * TT + t) * EE + h * DHS + c] = o[i][j] * inv;
        }
    }
}

// ---------------- LayerNorm over last dim (1024), one block per row --------
__global__ __launch_bounds__(256) void ln_kernel(
    const float* __restrict__ in, const float* __restrict__ g,
    const float* __restrict__ be, float* __restrict__ out)
{
    const int row = blockIdx.x;
    const int tid = threadIdx.x;
    const float4* p = (const float4*)(in + row * EE);
    float4 x = p[tid];
    float s  = x.x + x.y + x.z + x.w;
    float ss = x.x * x.x + x.y * x.y + x.z * x.z + x.w * x.w;
    #pragma unroll
    for (int off = 16; off >= 1; off >>= 1) {
        s  += __shfl_xor_sync(0xffffffffu, s,  off);
        ss += __shfl_xor_sync(0xffffffffu, ss, off);
    }
    __shared__ float ws[8], wss[8];
    int w = tid >> 5, ln = tid & 31;
    if (ln == 0) { ws[w] = s; wss[w] = ss; }
    __syncthreads();
    s = 0.0f; ss = 0.0f;
    #pragma unroll
    for (int i = 0; i < 8; i++) { s += ws[i]; ss += wss[i]; }
    const float mu  = s * (1.0f / EE);
    const float var = ss * (1.0f / EE) - mu * mu;
    const float rs  = rsqrtf(var + 1e-5f);
    float4 gg = ((const float4*)g)[tid];
    float4 bb = ((const float4*)be)[tid];
    float4 y;
    y.x = (x.x - mu) * rs * gg.x + bb.x;
    y.y = (x.y - mu) * rs * gg.y + bb.y;
    y.z = (x.z - mu) * rs * gg.z + bb.z;
    y.w = (x.w - mu) * rs * gg.w + bb.w;
    ((float4*)(out + row * EE))[tid] = y;
}

// ---------------- launch ----------------------------------------------------
#define ATTN_SMEM (4 * 64 * SSTR * 4)

extern "C" void kernel_launch(void* const* d_in, const int* in_sizes, int n_in,
                              void* d_out, int out_size)
{
    const float* x   = (const float*)d_in[0];
    const float* Wq  = (const float*)d_in[1];
    const float* Wk  = (const float*)d_in[2];
    const float* Wv  = (const float*)d_in[3];
    const float* Wo  = (const float*)d_in[4];
    const float* bo  = (const float*)d_in[5];
    const float* W1  = (const float*)d_in[6];
    const float* b1  = (const float*)d_in[7];
    const float* W2  = (const float*)d_in[8];
    const float* b2  = (const float*)d_in[9];
    const float* g1  = (const float*)d_in[10];
    const float* be1 = (const float*)d_in[11];
    const float* g2  = (const float*)d_in[12];
    const float* be2 = (const float*)d_in[13];
    float* out = (float*)d_out;

    float *Op, *t1, *x1, *hp;
    cudaGetSymbolAddress((void**)&Op, g_O);
    cudaGetSymbolAddress((void**)&t1, g_t1);
    cudaGetSymbolAddress((void**)&x1, g_x1);
    cudaGetSymbolAddress((void**)&hp, g_h);

    cudaFuncSetAttribute(attn_kernel,
                         cudaFuncAttributeMaxDynamicSharedMemorySize, ATTN_SMEM);

    // 1. QKV projections -> g_Q/g_K/g_V [B,H,T,64]
    gemm_qkv<<<dim3(8, 32, 3), 256>>>(x, Wq, Wk, Wv);
    // 2. causal attention -> g_O [B*T, E] (concat heads)
    attn_kernel<<<dim3(32, 16, 2), 256, ATTN_SMEM>>>(Op);
    // 3. out proj + bias + residual -> t1
    gemm_rm<0><<<dim3(8, 32), 256>>>(Op, Wo, bo, x, t1, MTOT, 1024, 1024);
    // 4. LN1 -> x1
    ln_kernel<<<MTOT, 256>>>(t1, g1, be1, x1);
    // 5. FFN up + relu -> g_h [4096,4096]
    gemm_rm<1><<<dim3(32, 32), 256>>>(x1, W1, b1, nullptr, hp, MTOT, 4096, 1024);
    // 6. FFN down + bias + residual -> t1
    gemm_rm<0><<<dim3(8, 32), 256>>>(hp, W2, b2, x1, t1, MTOT, 1024, 4096);
    // 7. LN2 -> output
    ln_kernel<<<MTOT, 256>>>(t1, g2, be2, out);
}

// round 2
// speedup vs baseline: 1.2790x; 1.2790x over previous
#include <cuda_runtime.h>

// Problem constants
#define BB 2
#define TT 2048
#define EE 1024
#define HH 16
#define DHS 64
#define MTOT (BB*TT)          // 4096 rows

// ---------------- scratch (device globals; no allocation) ----------------
__device__ float g_Q[BB*HH*TT*DHS];     // [B,H,T,64]
__device__ float g_K[BB*HH*TT*DHS];
__device__ float g_V[BB*HH*TT*DHS];
__device__ float g_O[MTOT*EE];          // attention output, concat layout [B*T, E]
__device__ float g_t1[MTOT*EE];         // pre-LN buffer
__device__ float g_x1[MTOT*EE];         // post-LN1
__device__ float g_h[MTOT*4*EE];        // FFN hidden [4096, 4096]

// ---------------- tf32 helpers ---------------------------------------------
__device__ __forceinline__ unsigned f2tf(float f) {
    unsigned u;
    asm("cvt.rna.tf32.f32 %0, %1;" : "=r"(u) : "f"(f));
    return u;
}

__device__ __forceinline__ void mma8(float* c, const unsigned* a, const unsigned* b) {
    asm volatile(
        "mma.sync.aligned.m16n8k8.row.col.f32.tf32.tf32.f32 "
        "{%0,%1,%2,%3},{%4,%5,%6,%7},{%8,%9},{%0,%1,%2,%3};"
        : "+f"(c[0]), "+f"(c[1]), "+f"(c[2]), "+f"(c[3])
        : "r"(a[0]), "r"(a[1]), "r"(a[2]), "r"(a[3]), "r"(b[0]), "r"(b[1]));
}

// ---------------- tf32 tensor-core GEMM -------------------------------------
// C[M,N] = A[M,K] @ B[K,N] (+ epilogue). 128x128x32 tile, 256 threads, 8 warps.
// MODE 0: QKV — B select by blockIdx.z from W[H,E,HS]; scatter-write Q/K/V [B,H,T,64]
// MODE 1: C = A@B + bias + res
// MODE 2: C = relu(A@B + bias)
#define SA 36     // A smem stride (words): bank = 4*m + k -> conflict-free frags
#define SB 136    // B smem stride (words): bank = 8*k + n -> conflict-free frags

template <int MODE>
__global__ __launch_bounds__(256, 1) void gemm_tf32(
    const float* __restrict__ A,
    const float* __restrict__ B0, const float* __restrict__ B1,
    const float* __restrict__ B2,
    const float* __restrict__ bias, const float* __restrict__ res,
    float* __restrict__ C, int M, int N, int K)
{
    __shared__ __align__(16) unsigned As[128 * SA];
    __shared__ __align__(16) unsigned Bs[32 * SB];

    const int tid  = threadIdx.x;
    const int lane = tid & 31;
    const int g    = lane >> 2;        // groupID (0..7)
    const int tg   = lane & 3;         // thread-in-group (0..3)
    const int wid  = tid >> 5;
    const int wm   = (wid & 1) * 64;   // warp m offset
    const int wn   = (wid >> 1) * 32;  // warp n offset
    const int bm   = blockIdx.y * 128;
    const int bn   = blockIdx.x * 128;

    const float* Bw = B0;
    if (MODE == 0) Bw = (blockIdx.z == 0) ? B0 : (blockIdx.z == 1) ? B1 : B2;

    // staging indices
    // A: 128x32 floats = 1024 float4, 4 per thread
    const int arow0 = tid >> 3;            // 0..31 (+32*i)
    const int acol  = (tid & 7) * 4;
    // B: 32x128 floats = 1024 float4, 4 per thread
    const int bk0   = tid >> 5;            // 0..7 (+8*i)
    const int bn0   = (tid & 31) * 4;

    float4 ar[4], br[4];

    auto load_tile = [&](int k0) {
        #pragma unroll
        for (int i = 0; i < 4; i++) {
            int r = arow0 + i * 32;
            ar[i] = *(const float4*)&A[(size_t)(bm + r) * K + k0 + acol];
        }
        #pragma unroll
        for (int i = 0; i < 4; i++) {
            int kr = bk0 + i * 8;
            if (MODE == 0) {
                int n = bn + bn0;
                br[i] = *(const float4*)&Bw[((n >> 6) << 16) + (k0 + kr) * 64 + (n & 63)];
            } else {
                br[i] = *(const float4*)&Bw[(size_t)(k0 + kr) * N + bn + bn0];
            }
        }
    };

    auto store_tile = [&]() {
        #pragma unroll
        for (int i = 0; i < 4; i++) {
            int r = arow0 + i * 32;
            uint4 u = make_uint4(f2tf(ar[i].x), f2tf(ar[i].y), f2tf(ar[i].z), f2tf(ar[i].w));
            *(uint4*)&As[r * SA + acol] = u;
        }
        #pragma unroll
        for (int i = 0; i < 4; i++) {
            int kr = bk0 + i * 8;
            uint4 u = make_uint4(f2tf(br[i].x), f2tf(br[i].y), f2tf(br[i].z), f2tf(br[i].w));
            *(uint4*)&Bs[kr * SB + bn0] = u;
        }
    };

    float acc[4][4][4];
    #pragma unroll
    for (int mi = 0; mi < 4; mi++)
        #pragma unroll
        for (int ni = 0; ni < 4; ni++)
            #pragma unroll
            for (int r = 0; r < 4; r++) acc[mi][ni][r] = 0.0f;

    const int nt = K >> 5;
    load_tile(0);
    for (int t = 0; t < nt; t++) {
        __syncthreads();
        store_tile();
        __syncthreads();
        if (t + 1 < nt) load_tile((t + 1) << 5);

        #pragma unroll
        for (int ks = 0; ks < 4; ks++) {
            const int kk = ks * 8;
            unsigned af[4][4];
            #pragma unroll
            for (int mi = 0; mi < 4; mi++) {
                int row = wm + mi * 16;
                af[mi][0] = As[(row + g) * SA + kk + tg];
                af[mi][1] = As[(row + 8 + g) * SA + kk + tg];
                af[mi][2] = As[(row + g) * SA + kk + 4 + tg];
                af[mi][3] = As[(row + 8 + g) * SA + kk + 4 + tg];
            }
            unsigned bf[4][2];
            #pragma unroll
            for (int ni = 0; ni < 4; ni++) {
                int col = wn + ni * 8 + g;
                bf[ni][0] = Bs[(kk + tg) * SB + col];
                bf[ni][1] = Bs[(kk + 4 + tg) * SB + col];
            }
            #pragma unroll
            for (int mi = 0; mi < 4; mi++)
                #pragma unroll
                for (int ni = 0; ni < 4; ni++)
                    mma8(acc[mi][ni], af[mi], bf[ni]);
        }
    }

    // epilogue
    #pragma unroll
    for (int mi = 0; mi < 4; mi++) {
        #pragma unroll
        for (int r2 = 0; r2 < 2; r2++) {
            int m = bm + wm + mi * 16 + g + r2 * 8;
            #pragma unroll
            for (int ni = 0; ni < 4; ni++) {
                int n = bn + wn + ni * 8 + tg * 2;
                float v0 = acc[mi][ni][r2 * 2 + 0];
                float v1 = acc[mi][ni][r2 * 2 + 1];
                if (MODE == 0) {
                    float* Ob = (blockIdx.z == 0) ? g_Q : (blockIdx.z == 1) ? g_K : g_V;
                    int b = m >> 11, tt = m & 2047;
                    int hh = n >> 6, dd = n & 63;
                    float* p = &Ob[(((b * HH + hh) * TT + tt) * DHS) + dd];
                    p[0] = v0; p[1] = v1;
                } else {
                    v0 += bias[n]; v1 += bias[n + 1];
                    if (MODE == 1) {
                        v0 += res[(size_t)m * N + n];
                        v1 += res[(size_t)m * N + n + 1];
                    } else {
                        v0 = fmaxf(v0, 0.0f); v1 = fmaxf(v1, 0.0f);
                    }
                    C[(size_t)m * N + n] = v0;
                    C[(size_t)m * N + n + 1] = v1;
                }
            }
        }
    }
}

// ---------------- fused causal flash attention -----------------------------
// grid (T/64=32, H=16, B=2), block 256, dynamic smem 4*64*65*4 = 66560 B
#define SSTR 65
__global__ __launch_bounds__(256) void attn_kernel(float* __restrict__ Ocat)
{
    extern __shared__ float sm[];
    float* Qs = sm;
    float* Ks = sm + 64 * SSTR;
    float* Vs = sm + 2 * 64 * SSTR;
    float* Ps = sm + 3 * 64 * SSTR;

    const int qt = blockIdx.x, h = blockIdx.y, b = blockIdx.z;
    const int tid = threadIdx.x, ty = tid >> 4, tx = tid & 15;
    const int base = ((b * HH + h) * TT) * DHS;
    const float* Qg = g_Q + base;
    const float* Kg = g_K + base;
    const float* Vg = g_V + base;

    #pragma unroll
    for (int i = 0; i < 4; i++) {
        int idx = tid + i * 256;
        int r = idx >> 4, c = (idx & 15) * 4;
        float4 v = *(const float4*)&Qg[(qt * 64 + r) * 64 + c];
        Qs[r * SSTR + c + 0] = v.x * 0.125f;
        Qs[r * SSTR + c + 1] = v.y * 0.125f;
        Qs[r * SSTR + c + 2] = v.z * 0.125f;
        Qs[r * SSTR + c + 3] = v.w * 0.125f;
    }

    float m_i[4], l_i[4], o[4][4];
    #pragma unroll
    for (int i = 0; i < 4; i++) {
        m_i[i] = -1e30f; l_i[i] = 0.0f;
        #pragma unroll
        for (int j = 0; j < 4; j++) o[i][j] = 0.0f;
    }

    for (int kt = 0; kt <= qt; kt++) {
        __syncthreads();
        #pragma unroll
        for (int i = 0; i < 4; i++) {
            int idx = tid + i * 256;
            int r = idx >> 4, c = (idx & 15) * 4;
            float4 kv = *(const float4*)&Kg[(kt * 64 + r) * 64 + c];
            Ks[r * SSTR + c + 0] = kv.x; Ks[r * SSTR + c + 1] = kv.y;
            Ks[r * SSTR + c + 2] = kv.z; Ks[r * SSTR + c + 3] = kv.w;
            float4 vv = *(const float4*)&Vg[(kt * 64 + r) * 64 + c];
            Vs[r * SSTR + c + 0] = vv.x; Vs[r * SSTR + c + 1] = vv.y;
            Vs[r * SSTR + c + 2] = vv.z; Vs[r * SSTR + c + 3] = vv.w;
        }
        __syncthreads();

        float s[4][4] = {};
        #pragma unroll 8
        for (int k = 0; k < 64; k++) {
            float qv[4], kv[4];
            #pragma unroll
            for (int i = 0; i < 4; i++) qv[i] = Qs[(4 * ty + i) * SSTR + k];
            #pragma unroll
            for (int j = 0; j < 4; j++) kv[j] = Ks[(4 * tx + j) * SSTR + k];
            #pragma unroll
            for (int i = 0; i < 4; i++)
                #pragma unroll
                for (int j = 0; j < 4; j++) s[i][j] += qv[i] * kv[j];
        }
        if (kt == qt) {
            #pragma unroll
            for (int i = 0; i < 4; i++)
                #pragma unroll
                for (int j = 0; j < 4; j++)
                    if (4 * tx + j > 4 * ty + i) s[i][j] = -1e30f;
        }
        #pragma unroll
        for (int i = 0; i < 4; i++) {
            float rm = s[i][0];
            #pragma unroll
            for (int j = 1; j < 4; j++) rm = fmaxf(rm, s[i][j]);
            #pragma unroll
            for (int off = 8; off >= 1; off >>= 1)
                rm = fmaxf(rm, __shfl_xor_sync(0xffffffffu, rm, off));
            float mn = fmaxf(m_i[i], rm);
            float alpha = __expf(m_i[i] - mn);
            m_i[i] = mn;
            float rs = 0.0f;
            #pragma unroll
            for (int j = 0; j < 4; j++) {
                s[i][j] = __expf(s[i][j] - mn);
                rs += s[i][j];
            }
            #pragma unroll
            for (int off = 8; off >= 1; off >>= 1)
                rs += __shfl_xor_sync(0xffffffffu, rs, off);
            l_i[i] = l_i[i] * alpha + rs;
            #pragma unroll
            for (int j = 0; j < 4; j++) {
                o[i][j] *= alpha;
                Ps[(4 * ty + i) * SSTR + 4 * tx + j] = s[i][j];
            }
        }
        __syncthreads();
        #pragma unroll 8
        for (int k = 0; k < 64; k++) {
            float pv[4], vv[4];
            #pragma unroll
            for (int i = 0; i < 4; i++) pv[i] = Ps[(4 * ty + i) * SSTR + k];
            #pragma unroll
            for (int j = 0; j < 4; j++) vv[j] = Vs[k * SSTR + 4 * tx + j];
            #pragma unroll
            for (int i = 0; i < 4; i++)
                #pragma unroll
                for (int j = 0; j < 4; j++) o[i][j] += pv[i] * vv[j];
        }
    }
    #pragma unroll
    for (int i = 0; i < 4; i++) {
        int t = qt * 64 + 4 * ty + i;
        float inv = 1.0f / l_i[i];
        #pragma unroll
        for (int j = 0; j < 4; j++) {
            int c = 4 * tx + j;
            Ocat[(b * TT + t) * EE + h * DHS + c] = o[i][j] * inv;
        }
    }
}

// ---------------- LayerNorm over last dim (1024), one block per row --------
__global__ __launch_bounds__(256) void ln_kernel(
    const float* __restrict__ in, const float* __restrict__ g,
    const float* __restrict__ be, float* __restrict__ out)
{
    const int row = blockIdx.x;
    const int tid = threadIdx.x;
    const float4* p = (const float4*)(in + row * EE);
    float4 x = p[tid];
    float s  = x.x + x.y + x.z + x.w;
    float ss = x.x * x.x + x.y * x.y + x.z * x.z + x.w * x.w;
    #pragma unroll
    for (int off = 16; off >= 1; off >>= 1) {
        s  += __shfl_xor_sync(0xffffffffu, s,  off);
        ss += __shfl_xor_sync(0xffffffffu, ss, off);
    }
    __shared__ float ws[8], wss[8];
    int w = tid >> 5, ln = tid & 31;
    if (ln == 0) { ws[w] = s; wss[w] = ss; }
    __syncthreads();
    s = 0.0f; ss = 0.0f;
    #pragma unroll
    for (int i = 0; i < 8; i++) { s += ws[i]; ss += wss[i]; }
    const float mu  = s * (1.0f / EE);
    const float var = ss * (1.0f / EE) - mu * mu;
    const float rs  = rsqrtf(var + 1e-5f);
    float4 gg = ((const float4*)g)[tid];
    float4 bb = ((const float4*)be)[tid];
    float4 y;
    y.x = (x.x - mu) * rs * gg.x + bb.x;
    y.y = (x.y - mu) * rs * gg.y + bb.y;
    y.z = (x.z - mu) * rs * gg.z + bb.z;
    y.w = (x.w - mu) * rs * gg.w + bb.w;
    ((float4*)(out + row * EE))[tid] = y;
}

// ---------------- launch ----------------------------------------------------
#define ATTN_SMEM (4 * 64 * SSTR * 4)

extern "C" void kernel_launch(void* const* d_in, const int* in_sizes, int n_in,
                              void* d_out, int out_size)
{
    const float* x   = (const float*)d_in[0];
    const float* Wq  = (const float*)d_in[1];
    const float* Wk  = (const float*)d_in[2];
    const float* Wv  = (const float*)d_in[3];
    const float* Wo  = (const float*)d_in[4];
    const float* bo  = (const float*)d_in[5];
    const float* W1  = (const float*)d_in[6];
    const float* b1  = (const float*)d_in[7];
    const float* W2  = (const float*)d_in[8];
    const float* b2  = (const float*)d_in[9];
    const float* g1  = (const float*)d_in[10];
    const float* be1 = (const float*)d_in[11];
    const float* g2  = (const float*)d_in[12];
    const float* be2 = (const float*)d_in[13];
    float* out = (float*)d_out;

    float *Op, *t1, *x1, *hp;
    cudaGetSymbolAddress((void**)&Op, g_O);
    cudaGetSymbolAddress((void**)&t1, g_t1);
    cudaGetSymbolAddress((void**)&x1, g_x1);
    cudaGetSymbolAddress((void**)&hp, g_h);

    cudaFuncSetAttribute(attn_kernel,
                         cudaFuncAttributeMaxDynamicSharedMemorySize, ATTN_SMEM);

    // 1. QKV projections (tf32 TC) -> g_Q/g_K/g_V [B,H,T,64]
    gemm_tf32<0><<<dim3(8, 32, 3), 256>>>(x, Wq, Wk, Wv, nullptr, nullptr,
                                          nullptr, MTOT, 1024, 1024);
    // 2. causal attention -> g_O [B*T, E]
    attn_kernel<<<dim3(32, 16, 2), 256, ATTN_SMEM>>>(Op);
    // 3. out proj + bias + residual -> t1
    gemm_tf32<1><<<dim3(8, 32, 1), 256>>>(Op, Wo, nullptr, nullptr, bo, x,
                                          t1, MTOT, 1024, 1024);
    // 4. LN1 -> x1
    ln_kernel<<<MTOT, 256>>>(t1, g1, be1, x1);
    // 5. FFN up + relu -> g_h [4096,4096]
    gemm_tf32<2><<<dim3(32, 32, 1), 256>>>(x1, W1, nullptr, nullptr, b1, nullptr,
                                           hp, MTOT, 4096, 1024);
    // 6. FFN down + bias + residual -> t1
    gemm_tf32<1><<<dim3(8, 32, 1), 256>>>(hp, W2, nullptr, nullptr, b2, x1,
                                          t1, MTOT, 1024, 4096);
    // 7. LN2 -> output
    ln_kernel<<<MTOT, 256>>>(t1, g2, be2, out);
}

// round 3
// speedup vs baseline: 3.1758x; 2.4831x over previous
#include <cuda_runtime.h>

// Problem constants
#define BB 2
#define TT 2048
#define EE 1024
#define HH 16
#define DHS 64
#define MTOT (BB*TT)          // 4096 rows

// ---------------- scratch (device globals; no allocation) ----------------
__device__ float g_Q[BB*HH*TT*DHS];     // [B,H,T,64]
__device__ float g_K[BB*HH*TT*DHS];
__device__ float g_V[BB*HH*TT*DHS];
__device__ float g_O[MTOT*EE];          // attention output [B*T, E]
__device__ float g_t1[MTOT*EE];
__device__ float g_x1[MTOT*EE];
__device__ float g_h[MTOT*4*EE];        // FFN hidden [4096, 4096]

// ---------------- helpers ---------------------------------------------------
__device__ __forceinline__ unsigned f2tf(float f) {
    unsigned u;
    asm("cvt.rna.tf32.f32 %0, %1;" : "=r"(u) : "f"(f));
    return u;
}

__device__ __forceinline__ void mma8(float* c, const unsigned* a, const unsigned* b) {
    asm volatile(
        "mma.sync.aligned.m16n8k8.row.col.f32.tf32.tf32.f32 "
        "{%0,%1,%2,%3},{%4,%5,%6,%7},{%8,%9},{%0,%1,%2,%3};"
        : "+f"(c[0]), "+f"(c[1]), "+f"(c[2]), "+f"(c[3])
        : "r"(a[0]), "r"(a[1]), "r"(a[2]), "r"(a[3]), "r"(b[0]), "r"(b[1]));
}

__device__ __forceinline__ void cp16(void* dst, const void* src) {
    unsigned d = (unsigned)__cvta_generic_to_shared(dst);
    asm volatile("cp.async.cg.shared.global [%0], [%1], 16;" :: "r"(d), "l"(src));
}

// ---------------- tf32 tensor-core GEMM, cp.async double-buffered ----------
// C[M,N] = A[M,K] @ B[K,N] (+ epilogue). 128x128x32 tile, 256 threads.
// MODE 0: QKV — B select by blockIdx.z from W[H,E,HS]; scatter-write [B,H,T,64]
// MODE 1: C = A@B + bias + res
// MODE 2: C = relu(A@B + bias)
#define SA 36     // A smem stride (words): conflict-free frag loads
#define SB 136    // B smem stride (words): conflict-free frag loads
#define GEMM_SMEM ((2*128*SA + 2*32*SB)*4)

template <int MODE>
__global__ __launch_bounds__(256, 1) void gemm_tf32(
    const float* __restrict__ A,
    const float* __restrict__ B0, const float* __restrict__ B1,
    const float* __restrict__ B2,
    const float* __restrict__ bias, const float* __restrict__ res,
    float* __restrict__ C, int M, int N, int K)
{
    extern __shared__ float smem[];
    float* As = smem;                 // [2][128*SA]
    float* Bs = smem + 2 * 128 * SA;  // [2][32*SB]

    const int tid  = threadIdx.x;
    const int lane = tid & 31;
    const int g    = lane >> 2;
    const int tg   = lane & 3;
    const int wid  = tid >> 5;
    const int wm   = (wid & 1) * 64;
    const int wn   = (wid >> 1) * 32;
    const int bm   = blockIdx.y * 128;
    const int bn   = blockIdx.x * 128;

    const float* Bw = B0;
    if (MODE == 0) Bw = (blockIdx.z == 0) ? B0 : (blockIdx.z == 1) ? B1 : B2;

    const int arow0 = tid >> 3;            // 0..31 (+32*i)
    const int acol  = (tid & 7) * 4;
    const int bk0   = tid >> 5;            // 0..7 (+8*i)
    const int bn0   = (tid & 31) * 4;

    auto issue = [&](int t) {
        const int k0 = t << 5, buf = t & 1;
        float* Ad = As + buf * 128 * SA;
        float* Bd = Bs + buf * 32 * SB;
        #pragma unroll
        for (int i = 0; i < 4; i++) {
            int r = arow0 + i * 32;
            cp16(&Ad[r * SA + acol], &A[(size_t)(bm + r) * K + k0 + acol]);
        }
        #pragma unroll
        for (int i = 0; i < 4; i++) {
            int kr = bk0 + i * 8;
            const float* src;
            if (MODE == 0) {
                int n = bn + bn0;
                src = &Bw[((n >> 6) << 16) + (k0 + kr) * 64 + (n & 63)];
            } else {
                src = &Bw[(size_t)(k0 + kr) * N + bn + bn0];
            }
            cp16(&Bd[kr * SB + bn0], src);
        }
        asm volatile("cp.async.commit_group;");
    };

    float acc[4][4][4] = {};
    const int nt = K >> 5;
    issue(0);
    for (int t = 0; t < nt; t++) {
        if (t + 1 < nt) {
            issue(t + 1);
            asm volatile("cp.async.wait_group 1;");
        } else {
            asm volatile("cp.async.wait_group 0;");
        }
        __syncthreads();
        const unsigned* Au = (const unsigned*)(As + (t & 1) * 128 * SA);
        const unsigned* Bu = (const unsigned*)(Bs + (t & 1) * 32 * SB);

        #pragma unroll
        for (int ks = 0; ks < 4; ks++) {
            const int kk = ks * 8;
            unsigned af[4][4];
            #pragma unroll
            for (int mi = 0; mi < 4; mi++) {
                int row = wm + mi * 16;
                af[mi][0] = Au[(row + g) * SA + kk + tg];
                af[mi][1] = Au[(row + 8 + g) * SA + kk + tg];
                af[mi][2] = Au[(row + g) * SA + kk + 4 + tg];
                af[mi][3] = Au[(row + 8 + g) * SA + kk + 4 + tg];
            }
            unsigned bf[4][2];
            #pragma unroll
            for (int ni = 0; ni < 4; ni++) {
                int col = wn + ni * 8 + g;
                bf[ni][0] = Bu[(kk + tg) * SB + col];
                bf[ni][1] = Bu[(kk + 4 + tg) * SB + col];
            }
            #pragma unroll
            for (int mi = 0; mi < 4; mi++)
                #pragma unroll
                for (int ni = 0; ni < 4; ni++)
                    mma8(acc[mi][ni], af[mi], bf[ni]);
        }
        __syncthreads();
    }

    // epilogue
    #pragma unroll
    for (int mi = 0; mi < 4; mi++) {
        #pragma unroll
        for (int r2 = 0; r2 < 2; r2++) {
            int m = bm + wm + mi * 16 + g + r2 * 8;
            #pragma unroll
            for (int ni = 0; ni < 4; ni++) {
                int n = bn + wn + ni * 8 + tg * 2;
                float v0 = acc[mi][ni][r2 * 2 + 0];
                float v1 = acc[mi][ni][r2 * 2 + 1];
                if (MODE == 0) {
                    float* Ob = (blockIdx.z == 0) ? g_Q : (blockIdx.z == 1) ? g_K : g_V;
                    int b = m >> 11, tt = m & 2047;
                    int hh = n >> 6, dd = n & 63;
                    float* p = &Ob[(((b * HH + hh) * TT + tt) * DHS) + dd];
                    p[0] = v0; p[1] = v1;
                } else {
                    v0 += bias[n]; v1 += bias[n + 1];
                    if (MODE == 1) {
                        v0 += res[(size_t)m * N + n];
                        v1 += res[(size_t)m * N + n + 1];
                    } else {
                        v0 = fmaxf(v0, 0.0f); v1 = fmaxf(v1, 0.0f);
                    }
                    C[(size_t)m * N + n] = v0;
                    C[(size_t)m * N + n + 1] = v1;
                }
            }
        }
    }
}

// ---------------- tensor-core causal flash attention ------------------------
// grid (T/64=32, H=16, B=2), block 128 (4 warps), warp owns 16 Q rows.
#define AST 68
#define ATTN_SMEM (4 * 64 * AST * 4)   // 69632 B

__global__ __launch_bounds__(128) void attn_kernel(float* __restrict__ Ocat)
{
    extern __shared__ float sm[];
    float* Qs = sm;
    float* Ks = sm + 64 * AST;
    float* Vs = sm + 2 * 64 * AST;
    float* Ps = sm + 3 * 64 * AST;

    const int qt = blockIdx.x, h = blockIdx.y, b = blockIdx.z;
    const int tid = threadIdx.x, wid = tid >> 5, lane = tid & 31;
    const int g = lane >> 2, tg = lane & 3;
    const int wm = wid * 16;
    const size_t base = ((size_t)(b * HH + h)) * TT * DHS;
    const float* Qg = g_Q + base;
    const float* Kg = g_K + base;
    const float* Vg = g_V + base;

    // load Q tile (scaled by 1/sqrt(64)), rna->tf32 at store
    #pragma unroll
    for (int i = 0; i < 8; i++) {
        int idx = tid + i * 128;
        int r = idx >> 4, c = (idx & 15) * 4;
        float4 v = *(const float4*)&Qg[(qt * 64 + r) * 64 + c];
        unsigned* q = (unsigned*)&Qs[r * AST + c];
        q[0] = f2tf(v.x * 0.125f); q[1] = f2tf(v.y * 0.125f);
        q[2] = f2tf(v.z * 0.125f); q[3] = f2tf(v.w * 0.125f);
    }

    float m_i[2] = {-1e30f, -1e30f}, l_i[2] = {0.0f, 0.0f};
    float o[8][4];
    #pragma unroll
    for (int ni = 0; ni < 8; ni++)
        #pragma unroll
        for (int e = 0; e < 4; e++) o[ni][e] = 0.0f;

    const unsigned* Qu = (const unsigned*)Qs;
    const unsigned* Ku = (const unsigned*)Ks;
    const unsigned* Vu = (const unsigned*)Vs;
    const unsigned* Pu = (const unsigned*)Ps;

    for (int kt = 0; kt <= qt; kt++) {
        __syncthreads();
        #pragma unroll
        for (int i = 0; i < 8; i++) {
            int idx = tid + i * 128;
            int r = idx >> 4, c = (idx & 15) * 4;
            float4 kv = *(const float4*)&Kg[(kt * 64 + r) * 64 + c];
            unsigned* kd = (unsigned*)&Ks[r * AST + c];
            kd[0] = f2tf(kv.x); kd[1] = f2tf(kv.y);
            kd[2] = f2tf(kv.z); kd[3] = f2tf(kv.w);
            float4 vv = *(const float4*)&Vg[(kt * 64 + r) * 64 + c];
            unsigned* vd = (unsigned*)&Vs[r * AST + c];
            vd[0] = f2tf(vv.x); vd[1] = f2tf(vv.y);
            vd[2] = f2tf(vv.z); vd[3] = f2tf(vv.w);
        }
        __syncthreads();

        // S = Q K^T  (warp: 16 rows x 64 cols)
        float s[8][4] = {};
        #pragma unroll
        for (int ks = 0; ks < 8; ks++) {
            const int kk = ks * 8;
            unsigned aq[4];
            aq[0] = Qu[(wm + g) * AST + kk + tg];
            aq[1] = Qu[(wm + 8 + g) * AST + kk + tg];
            aq[2] = Qu[(wm + g) * AST + kk + 4 + tg];
            aq[3] = Qu[(wm + 8 + g) * AST + kk + 4 + tg];
            #pragma unroll
            for (int ni = 0; ni < 8; ni++) {
                unsigned bk[2];
                bk[0] = Ku[(ni * 8 + g) * AST + kk + tg];
                bk[1] = Ku[(ni * 8 + g) * AST + kk + 4 + tg];
                mma8(s[ni], aq, bk);
            }
        }
        // causal mask on diagonal tile
        if (kt == qt) {
            #pragma unroll
            for (int ni = 0; ni < 8; ni++)
                #pragma unroll
                for (int e = 0; e < 4; e++) {
                    int row = wm + g + ((e >= 2) ? 8 : 0);
                    int col = ni * 8 + tg * 2 + (e & 1);
                    if (col > row) s[ni][e] = -1e30f;
                }
        }
        // online softmax (rows g and g+8; quad lanes share a row)
        #pragma unroll
        for (int r2 = 0; r2 < 2; r2++) {
            float rm = -1e30f;
            #pragma unroll
            for (int ni = 0; ni < 8; ni++) {
                rm = fmaxf(rm, s[ni][2 * r2]);
                rm = fmaxf(rm, s[ni][2 * r2 + 1]);
            }
            rm = fmaxf(rm, __shfl_xor_sync(0xffffffffu, rm, 1));
            rm = fmaxf(rm, __shfl_xor_sync(0xffffffffu, rm, 2));
            float mn = fmaxf(m_i[r2], rm);
            float alpha = __expf(m_i[r2] - mn);
            m_i[r2] = mn;
            float rs = 0.0f;
            #pragma unroll
            for (int ni = 0; ni < 8; ni++) {
                float p0 = __expf(s[ni][2 * r2] - mn);
                float p1 = __expf(s[ni][2 * r2 + 1] - mn);
                s[ni][2 * r2] = p0; s[ni][2 * r2 + 1] = p1;
                rs += p0 + p1;
            }
            rs += __shfl_xor_sync(0xffffffffu, rs, 1);
            rs += __shfl_xor_sync(0xffffffffu, rs, 2);
            l_i[r2] = l_i[r2] * alpha + rs;
            #pragma unroll
            for (int ni = 0; ni < 8; ni++) {
                o[ni][2 * r2] *= alpha;
                o[ni][2 * r2 + 1] *= alpha;
            }
        }
        // store P (warp-private rows), reload as A-fragments
        unsigned* Pw = (unsigned*)Ps;
        #pragma unroll
        for (int ni = 0; ni < 8; ni++) {
            Pw[(wm + g) * AST + ni * 8 + tg * 2]         = f2tf(s[ni][0]);
            Pw[(wm + g) * AST + ni * 8 + tg * 2 + 1]     = f2tf(s[ni][1]);
            Pw[(wm + 8 + g) * AST + ni * 8 + tg * 2]     = f2tf(s[ni][2]);
            Pw[(wm + 8 + g) * AST + ni * 8 + tg * 2 + 1] = f2tf(s[ni][3]);
        }
        __syncwarp();
        // O += P V
        #pragma unroll
        for (int ks = 0; ks < 8; ks++) {
            const int kk = ks * 8;
            unsigned ap[4];
            ap[0] = Pu[(wm + g) * AST + kk + tg];
            ap[1] = Pu[(wm + 8 + g) * AST + kk + tg];
            ap[2] = Pu[(wm + g) * AST + kk + 4 + tg];
            ap[3] = Pu[(wm + 8 + g) * AST + kk + 4 + tg];
            #pragma unroll
            for (int ni = 0; ni < 8; ni++) {
                unsigned bv[2];
                bv[0] = Vu[(kk + tg) * AST + ni * 8 + g];
                bv[1] = Vu[(kk + 4 + tg) * AST + ni * 8 + g];
                mma8(o[ni], ap, bv);
            }
        }
    }

    // epilogue: concat layout Ocat[(b*T + t)*E + h*64 + col]
    const float inv0 = 1.0f / l_i[0], inv1 = 1.0f / l_i[1];
    #pragma unroll
    for (int ni = 0; ni < 8; ni++) {
        int t0 = qt * 64 + wm + g;
        int col = h * 64 + ni * 8 + tg * 2;
        float* p0 = &Ocat[((size_t)(b * TT + t0)) * EE + col];
        p0[0] = o[ni][0] * inv0; p0[1] = o[ni][1] * inv0;
        float* p1 = &Ocat[((size_t)(b * TT + t0 + 8)) * EE + col];
        p1[0] = o[ni][2] * inv1; p1[1] = o[ni][3] * inv1;
    }
}

// ---------------- LayerNorm over last dim (1024), one block per row --------
__global__ __launch_bounds__(256) void ln_kernel(
    const float* __restrict__ in, const float* __restrict__ g,
    const float* __restrict__ be, float* __restrict__ out)
{
    const int row = blockIdx.x;
    const int tid = threadIdx.x;
    const float4* p = (const float4*)(in + row * EE);
    float4 x = p[tid];
    float s  = x.x + x.y + x.z + x.w;
    float ss = x.x * x.x + x.y * x.y + x.z * x.z + x.w * x.w;
    #pragma unroll
    for (int off = 16; off >= 1; off >>= 1) {
        s  += __shfl_xor_sync(0xffffffffu, s,  off);
        ss += __shfl_xor_sync(0xffffffffu, ss, off);
    }
    __shared__ float ws[8], wss[8];
    int w = tid >> 5, ln = tid & 31;
    if (ln == 0) { ws[w] = s; wss[w] = ss; }
    __syncthreads();
    s = 0.0f; ss = 0.0f;
    #pragma unroll
    for (int i = 0; i < 8; i++) { s += ws[i]; ss += wss[i]; }
    const float mu  = s * (1.0f / EE);
    const float var = ss * (1.0f / EE) - mu * mu;
    const float rs  = rsqrtf(var + 1e-5f);
    float4 gg = ((const float4*)g)[tid];
    float4 bb = ((const float4*)be)[tid];
    float4 y;
    y.x = (x.x - mu) * rs * gg.x + bb.x;
    y.y = (x.y - mu) * rs * gg.y + bb.y;
    y.z = (x.z - mu) * rs * gg.z + bb.z;
    y.w = (x.w - mu) * rs * gg.w + bb.w;
    ((float4*)(out + row * EE))[tid] = y;
}

// ---------------- launch ----------------------------------------------------
extern "C" void kernel_launch(void* const* d_in, const int* in_sizes, int n_in,
                              void* d_out, int out_size)
{
    const float* x   = (const float*)d_in[0];
    const float* Wq  = (const float*)d_in[1];
    const float* Wk  = (const float*)d_in[2];
    const float* Wv  = (const float*)d_in[3];
    const float* Wo  = (const float*)d_in[4];
    const float* bo  = (const float*)d_in[5];
    const float* W1  = (const float*)d_in[6];
    const float* b1  = (const float*)d_in[7];
    const float* W2  = (const float*)d_in[8];
    const float* b2  = (const float*)d_in[9];
    const float* g1  = (const float*)d_in[10];
    const float* be1 = (const float*)d_in[11];
    const float* g2  = (const float*)d_in[12];
    const float* be2 = (const float*)d_in[13];
    float* out = (float*)d_out;

    float *Op, *t1, *x1, *hp;
    cudaGetSymbolAddress((void**)&Op, g_O);
    cudaGetSymbolAddress((void**)&t1, g_t1);
    cudaGetSymbolAddress((void**)&x1, g_x1);
    cudaGetSymbolAddress((void**)&hp, g_h);

    cudaFuncSetAttribute(gemm_tf32<0>,
                         cudaFuncAttributeMaxDynamicSharedMemorySize, GEMM_SMEM);
    cudaFuncSetAttribute(gemm_tf32<1>,
                         cudaFuncAttributeMaxDynamicSharedMemorySize, GEMM_SMEM);
    cudaFuncSetAttribute(gemm_tf32<2>,
                         cudaFuncAttributeMaxDynamicSharedMemorySize, GEMM_SMEM);
    cudaFuncSetAttribute(attn_kernel,
                         cudaFuncAttributeMaxDynamicSharedMemorySize, ATTN_SMEM);

    // 1. QKV projections (tf32 TC) -> g_Q/g_K/g_V [B,H,T,64]
    gemm_tf32<0><<<dim3(8, 32, 3), 256, GEMM_SMEM>>>(
        x, Wq, Wk, Wv, nullptr, nullptr, nullptr, MTOT, 1024, 1024);
    // 2. causal attention (tf32 TC) -> g_O [B*T, E]
    attn_kernel<<<dim3(32, 16, 2), 128, ATTN_SMEM>>>(Op);
    // 3. out proj + bias + residual -> t1
    gemm_tf32<1><<<dim3(8, 32, 1), 256, GEMM_SMEM>>>(
        Op, Wo, nullptr, nullptr, bo, x, t1, MTOT, 1024, 1024);
    // 4. LN1 -> x1
    ln_kernel<<<MTOT, 256>>>(t1, g1, be1, x1);
    // 5. FFN up + relu -> g_h [4096,4096]
    gemm_tf32<2><<<dim3(32, 32, 1), 256, GEMM_SMEM>>>(
        x1, W1, nullptr, nullptr, b1, nullptr, hp, MTOT, 4096, 1024);
    // 6. FFN down + bias + residual -> t1
    gemm_tf32<1><<<dim3(8, 32, 1), 256, GEMM_SMEM>>>(
        hp, W2, nullptr, nullptr, b2, x1, t1, MTOT, 1024, 4096);
    // 7. LN2 -> output
    ln_kernel<<<MTOT, 256>>>(t1, g2, be2, out);
}

// round 4
// speedup vs baseline: 3.2034x; 1.0087x over previous
#include <cuda_runtime.h>

// Problem constants
#define BB 2
#define TT 2048
#define EE 1024
#define HH 16
#define DHS 64
#define MTOT (BB*TT)          // 4096 rows

// ---------------- scratch (device globals; no allocation) ----------------
__device__ float g_Q[BB*HH*TT*DHS];     // [B,H,T,64]
__device__ float g_K[BB*HH*TT*DHS];
__device__ float g_V[BB*HH*TT*DHS];
__device__ float g_O[MTOT*EE];          // attention output [B*T, E]
__device__ float g_t1[MTOT*EE];
__device__ float g_x1[MTOT*EE];
__device__ float g_h[MTOT*4*EE];        // FFN hidden [4096, 4096]

// ---------------- helpers ---------------------------------------------------
__device__ __forceinline__ unsigned f2tf(float f) {
    unsigned u;
    asm("cvt.rna.tf32.f32 %0, %1;" : "=r"(u) : "f"(f));
    return u;
}

__device__ __forceinline__ void mma8(float* c, const unsigned* a, const unsigned* b) {
    asm volatile(
        "mma.sync.aligned.m16n8k8.row.col.f32.tf32.tf32.f32 "
        "{%0,%1,%2,%3},{%4,%5,%6,%7},{%8,%9},{%0,%1,%2,%3};"
        : "+f"(c[0]), "+f"(c[1]), "+f"(c[2]), "+f"(c[3])
        : "r"(a[0]), "r"(a[1]), "r"(a[2]), "r"(a[3]), "r"(b[0]), "r"(b[1]));
}

__device__ __forceinline__ void cp16(void* dst, const void* src) {
    unsigned d = (unsigned)__cvta_generic_to_shared(dst);
    asm volatile("cp.async.cg.shared.global [%0], [%1], 16;" :: "r"(d), "l"(src));
}

// ---------------- tf32 tensor-core GEMM, 3-stage cp.async ------------------
// C[M,N] = A[M,K] @ B[K,N] (+ epilogue). 128 x NT x 32 tile, 256 threads.
// MODE 0: QKV — B select by blockIdx.z from W[H,E,HS]; scatter-write [B,H,T,64]
// MODE 1: C = A@B + bias + res
// MODE 2: C = relu(A@B + bias)
#define SA 36               // A smem stride (words)
#define STAGES 3

template <int MODE, int NT>
__global__ __launch_bounds__(256, 1) void gemm_tf32(
    const float* __restrict__ A,
    const float* __restrict__ B0, const float* __restrict__ B1,
    const float* __restrict__ B2,
    const float* __restrict__ bias, const float* __restrict__ res,
    float* __restrict__ C, int M, int N, int K)
{
    constexpr int SB = NT + 8;          // B smem stride (words)
    constexpr int NI = NT / 32;         // n-frags per warp (warp n-width NT/4)
    constexpr int ASZ = 128 * SA;
    constexpr int BSZ = 32 * SB;

    extern __shared__ float smem[];
    float* As = smem;                   // [STAGES][ASZ]
    float* Bs = smem + STAGES * ASZ;    // [STAGES][BSZ]

    const int tid  = threadIdx.x;
    const int lane = tid & 31;
    const int g    = lane >> 2;
    const int tg   = lane & 3;
    const int wid  = tid >> 5;
    const int wm   = (wid & 1) * 64;
    const int wn   = (wid >> 1) * (NT / 4);
    const int bm   = blockIdx.y * 128;
    const int bn   = blockIdx.x * NT;

    const float* Bw = B0;
    if (MODE == 0) Bw = (blockIdx.z == 0) ? B0 : (blockIdx.z == 1) ? B1 : B2;

    auto issue = [&](int t) {
        const int k0 = t << 5, buf = t % STAGES;
        float* Ad = As + buf * ASZ;
        float* Bd = Bs + buf * BSZ;
        #pragma unroll
        for (int i = 0; i < 4; i++) {
            int e = tid + i * 256;            // float4 index in 128x32 tile
            int r = e >> 3, c = (e & 7) * 4;
            cp16(&Ad[r * SA + c], &A[(size_t)(bm + r) * K + k0 + c]);
        }
        #pragma unroll
        for (int i = 0; i < NT / 32; i++) {
            int e = tid + i * 256;            // float4 index in 32xNT tile
            int kr = e / (NT / 4), c = (e % (NT / 4)) * 4;
            const float* src;
            if (MODE == 0) {
                int n = bn + c;
                src = &Bw[((n >> 6) << 16) + (k0 + kr) * 64 + (n & 63)];
            } else {
                src = &Bw[(size_t)(k0 + kr) * N + bn + c];
            }
            cp16(&Bd[kr * SB + c], src);
        }
        asm volatile("cp.async.commit_group;");
    };

    float acc[4][NI][4];
    #pragma unroll
    for (int mi = 0; mi < 4; mi++)
        #pragma unroll
        for (int ni = 0; ni < NI; ni++)
            #pragma unroll
            for (int e = 0; e < 4; e++) acc[mi][ni][e] = 0.0f;

    const int nt = K >> 5;
    issue(0);
    issue(1);
    for (int t = 0; t < nt; t++) {
        asm volatile("cp.async.wait_group 1;");
        __syncthreads();
        if (t + 2 < nt) issue(t + 2);

        const unsigned* Au = (const unsigned*)(As + (t % STAGES) * ASZ);
        const unsigned* Bu = (const unsigned*)(Bs + (t % STAGES) * BSZ);

        #pragma unroll
        for (int ks = 0; ks < 4; ks++) {
            const int kk = ks * 8;
            unsigned af[4][4];
            #pragma unroll
            for (int mi = 0; mi < 4; mi++) {
                int row = wm + mi * 16;
                af[mi][0] = Au[(row + g) * SA + kk + tg];
                af[mi][1] = Au[(row + 8 + g) * SA + kk + tg];
                af[mi][2] = Au[(row + g) * SA + kk + 4 + tg];
                af[mi][3] = Au[(row + 8 + g) * SA + kk + 4 + tg];
            }
            unsigned bf[NI][2];
            #pragma unroll
            for (int ni = 0; ni < NI; ni++) {
                int col = wn + ni * 8 + g;
                bf[ni][0] = Bu[(kk + tg) * SB + col];
                bf[ni][1] = Bu[(kk + 4 + tg) * SB + col];
            }
            #pragma unroll
            for (int mi = 0; mi < 4; mi++)
                #pragma unroll
                for (int ni = 0; ni < NI; ni++)
                    mma8(acc[mi][ni], af[mi], bf[ni]);
        }
        __syncthreads();
    }

    // epilogue
    #pragma unroll
    for (int mi = 0; mi < 4; mi++) {
        #pragma unroll
        for (int r2 = 0; r2 < 2; r2++) {
            int m = bm + wm + mi * 16 + g + r2 * 8;
            #pragma unroll
            for (int ni = 0; ni < NI; ni++) {
                int n = bn + wn + ni * 8 + tg * 2;
                float v0 = acc[mi][ni][r2 * 2 + 0];
                float v1 = acc[mi][ni][r2 * 2 + 1];
                if (MODE == 0) {
                    float* Ob = (blockIdx.z == 0) ? g_Q : (blockIdx.z == 1) ? g_K : g_V;
                    int b = m >> 11, tt = m & 2047;
                    int hh = n >> 6, dd = n & 63;
                    float* p = &Ob[(((b * HH + hh) * TT + tt) * DHS) + dd];
                    p[0] = v0; p[1] = v1;
                } else {
                    v0 += bias[n]; v1 += bias[n + 1];
                    if (MODE == 1) {
                        v0 += res[(size_t)m * N + n];
                        v1 += res[(size_t)m * N + n + 1];
                    } else {
                        v0 = fmaxf(v0, 0.0f); v1 = fmaxf(v1, 0.0f);
                    }
                    C[(size_t)m * N + n] = v0;
                    C[(size_t)m * N + n + 1] = v1;
                }
            }
        }
    }
}

#define GEMM_SMEM_128 (STAGES * (128*SA + 32*(128+8)) * 4)
#define GEMM_SMEM_256 (STAGES * (128*SA + 32*(256+8)) * 4)

// ---------------- tensor-core causal flash attention ------------------------
// grid (T/64=32, H=16, B=2), block 128 (4 warps), warp owns 16 Q rows.
// K/V double-buffered via cp.async; raw fp32 (tf32 truncation).
#define AST 68
#define ATILE (64 * AST)
#define ATTN_SMEM (6 * ATILE * 4)   // Q + 2K + 2V + P = 104448 B

__global__ __launch_bounds__(128) void attn_kernel(float* __restrict__ Ocat)
{
    extern __shared__ float sm[];
    float* Qs = sm;
    float* Ks = sm + ATILE;          // [2][ATILE]
    float* Vs = sm + 3 * ATILE;      // [2][ATILE]
    float* Ps = sm + 5 * ATILE;

    const int qt = blockIdx.x, h = blockIdx.y, b = blockIdx.z;
    const int tid = threadIdx.x, wid = tid >> 5, lane = tid & 31;
    const int g = lane >> 2, tg = lane & 3;
    const int wm = wid * 16;
    const size_t base = ((size_t)(b * HH + h)) * TT * DHS;
    const float* Qg = g_Q + base;
    const float* Kg = g_K + base;
    const float* Vg = g_V + base;

    auto issue_kv = [&](int kt) {
        float* Kd = Ks + (kt & 1) * ATILE;
        float* Vd = Vs + (kt & 1) * ATILE;
        #pragma unroll
        for (int i = 0; i < 8; i++) {
            int idx = tid + i * 128;
            int r = idx >> 4, c = (idx & 15) * 4;
            cp16(&Kd[r * AST + c], &Kg[(kt * 64 + r) * 64 + c]);
            cp16(&Vd[r * AST + c], &Vg[(kt * 64 + r) * 64 + c]);
        }
        asm volatile("cp.async.commit_group;");
    };

    // load Q tile (scaled by 1/sqrt(64))
    #pragma unroll
    for (int i = 0; i < 8; i++) {
        int idx = tid + i * 128;
        int r = idx >> 4, c = (idx & 15) * 4;
        float4 v = *(const float4*)&Qg[(qt * 64 + r) * 64 + c];
        float* q = &Qs[r * AST + c];
        q[0] = v.x * 0.125f; q[1] = v.y * 0.125f;
        q[2] = v.z * 0.125f; q[3] = v.w * 0.125f;
    }
    issue_kv(0);

    float m_i[2] = {-1e30f, -1e30f}, l_i[2] = {0.0f, 0.0f};
    float o[8][4];
    #pragma unroll
    for (int ni = 0; ni < 8; ni++)
        #pragma unroll
        for (int e = 0; e < 4; e++) o[ni][e] = 0.0f;

    const unsigned* Qu = (const unsigned*)Qs;
    const unsigned* Pu = (const unsigned*)Ps;

    for (int kt = 0; kt <= qt; kt++) {
        __syncthreads();                       // buffer (kt+1)&1 free to overwrite
        if (kt + 1 <= qt) {
            issue_kv(kt + 1);
            asm volatile("cp.async.wait_group 1;");
        } else {
            asm volatile("cp.async.wait_group 0;");
        }
        __syncthreads();                       // visibility of buffer kt&1
        const unsigned* Ku = (const unsigned*)(Ks + (kt & 1) * ATILE);
        const unsigned* Vu = (const unsigned*)(Vs + (kt & 1) * ATILE);

        // S = Q K^T  (warp: 16 rows x 64 cols)
        float s[8][4] = {};
        #pragma unroll
        for (int ks = 0; ks < 8; ks++) {
            const int kk = ks * 8;
            unsigned aq[4];
            aq[0] = Qu[(wm + g) * AST + kk + tg];
            aq[1] = Qu[(wm + 8 + g) * AST + kk + tg];
            aq[2] = Qu[(wm + g) * AST + kk + 4 + tg];
            aq[3] = Qu[(wm + 8 + g) * AST + kk + 4 + tg];
            #pragma unroll
            for (int ni = 0; ni < 8; ni++) {
                unsigned bk[2];
                bk[0] = Ku[(ni * 8 + g) * AST + kk + tg];
                bk[1] = Ku[(ni * 8 + g) * AST + kk + 4 + tg];
                mma8(s[ni], aq, bk);
            }
        }
        if (kt == qt) {
            #pragma unroll
            for (int ni = 0; ni < 8; ni++)
                #pragma unroll
                for (int e = 0; e < 4; e++) {
                    int row = wm + g + ((e >= 2) ? 8 : 0);
                    int col = ni * 8 + tg * 2 + (e & 1);
                    if (col > row) s[ni][e] = -1e30f;
                }
        }
        // online softmax (rows g and g+8; quad lanes share a row)
        #pragma unroll
        for (int r2 = 0; r2 < 2; r2++) {
            float rm = -1e30f;
            #pragma unroll
            for (int ni = 0; ni < 8; ni++) {
                rm = fmaxf(rm, s[ni][2 * r2]);
                rm = fmaxf(rm, s[ni][2 * r2 + 1]);
            }
            rm = fmaxf(rm, __shfl_xor_sync(0xffffffffu, rm, 1));
            rm = fmaxf(rm, __shfl_xor_sync(0xffffffffu, rm, 2));
            float mn = fmaxf(m_i[r2], rm);
            float alpha = __expf(m_i[r2] - mn);
            m_i[r2] = mn;
            float rs = 0.0f;
            #pragma unroll
            for (int ni = 0; ni < 8; ni++) {
                float p0 = __expf(s[ni][2 * r2] - mn);
                float p1 = __expf(s[ni][2 * r2 + 1] - mn);
                s[ni][2 * r2] = p0; s[ni][2 * r2 + 1] = p1;
                rs += p0 + p1;
            }
            rs += __shfl_xor_sync(0xffffffffu, rs, 1);
            rs += __shfl_xor_sync(0xffffffffu, rs, 2);
            l_i[r2] = l_i[r2] * alpha + rs;
            #pragma unroll
            for (int ni = 0; ni < 8; ni++) {
                o[ni][2 * r2] *= alpha;
                o[ni][2 * r2 + 1] *= alpha;
            }
        }
        // store P (warp-private rows), reload as A-fragments
        unsigned* Pw = (unsigned*)Ps;
        #pragma unroll
        for (int ni = 0; ni < 8; ni++) {
            Pw[(wm + g) * AST + ni * 8 + tg * 2]         = f2tf(s[ni][0]);
            Pw[(wm + g) * AST + ni * 8 + tg * 2 + 1]     = f2tf(s[ni][1]);
            Pw[(wm + 8 + g) * AST + ni * 8 + tg * 2]     = f2tf(s[ni][2]);
            Pw[(wm + 8 + g) * AST + ni * 8 + tg * 2 + 1] = f2tf(s[ni][3]);
        }
        __syncwarp();
        // O += P V
        #pragma unroll
        for (int ks = 0; ks < 8; ks++) {
            const int kk = ks * 8;
            unsigned ap[4];
            ap[0] = Pu[(wm + g) * AST + kk + tg];
            ap[1] = Pu[(wm + 8 + g) * AST + kk + tg];
            ap[2] = Pu[(wm + g) * AST + kk + 4 + tg];
            ap[3] = Pu[(wm + 8 + g) * AST + kk + 4 + tg];
            #pragma unroll
            for (int ni = 0; ni < 8; ni++) {
                unsigned bv[2];
                bv[0] = Vu[(kk + tg) * AST + ni * 8 + g];
                bv[1] = Vu[(kk + 4 + tg) * AST + ni * 8 + g];
                mma8(o[ni], ap, bv);
            }
        }
    }

    // epilogue: concat layout Ocat[(b*T + t)*E + h*64 + col]
    const float inv0 = 1.0f / l_i[0], inv1 = 1.0f / l_i[1];
    #pragma unroll
    for (int ni = 0; ni < 8; ni++) {
        int t0 = qt * 64 + wm + g;
        int col = h * 64 + ni * 8 + tg * 2;
        float* p0 = &Ocat[((size_t)(b * TT + t0)) * EE + col];
        p0[0] = o[ni][0] * inv0; p0[1] = o[ni][1] * inv0;
        float* p1 = &Ocat[((size_t)(b * TT + t0 + 8)) * EE + col];
        p1[0] = o[ni][2] * inv1; p1[1] = o[ni][3] * inv1;
    }
}

// ---------------- LayerNorm over last dim (1024), one block per row --------
__global__ __launch_bounds__(256) void ln_kernel(
    const float* __restrict__ in, const float* __restrict__ g,
    const float* __restrict__ be, float* __restrict__ out)
{
    const int row = blockIdx.x;
    const int tid = threadIdx.x;
    const float4* p = (const float4*)(in + row * EE);
    float4 x = p[tid];
    float s  = x.x + x.y + x.z + x.w;
    float ss = x.x * x.x + x.y * x.y + x.z * x.z + x.w * x.w;
    #pragma unroll
    for (int off = 16; off >= 1; off >>= 1) {
        s  += __shfl_xor_sync(0xffffffffu, s,  off);
        ss += __shfl_xor_sync(0xffffffffu, ss, off);
    }
    __shared__ float ws[8], wss[8];
    int w = tid >> 5, ln = tid & 31;
    if (ln == 0) { ws[w] = s; wss[w] = ss; }
    __syncthreads();
    s = 0.0f; ss = 0.0f;
    #pragma unroll
    for (int i = 0; i < 8; i++) { s += ws[i]; ss += wss[i]; }
    const float mu  = s * (1.0f / EE);
    const float var = ss * (1.0f / EE) - mu * mu;
    const float rs  = rsqrtf(var + 1e-5f);
    float4 gg = ((const float4*)g)[tid];
    float4 bb = ((const float4*)be)[tid];
    float4 y;
    y.x = (x.x - mu) * rs * gg.x + bb.x;
    y.y = (x.y - mu) * rs * gg.y + bb.y;
    y.z = (x.z - mu) * rs * gg.z + bb.z;
    y.w = (x.w - mu) * rs * gg.w + bb.w;
    ((float4*)(out + row * EE))[tid] = y;
}

// ---------------- launch ----------------------------------------------------
extern "C" void kernel_launch(void* const* d_in, const int* in_sizes, int n_in,
                              void* d_out, int out_size)
{
    const float* x   = (const float*)d_in[0];
    const float* Wq  = (const float*)d_in[1];
    const float* Wk  = (const float*)d_in[2];
    const float* Wv  = (const float*)d_in[3];
    const float* Wo  = (const float*)d_in[4];
    const float* bo  = (const float*)d_in[5];
    const float* W1  = (const float*)d_in[6];
    const float* b1  = (const float*)d_in[7];
    const float* W2  = (const float*)d_in[8];
    const float* b2  = (const float*)d_in[9];
    const float* g1  = (const float*)d_in[10];
    const float* be1 = (const float*)d_in[11];
    const float* g2  = (const float*)d_in[12];
    const float* be2 = (const float*)d_in[13];
    float* out = (float*)d_out;

    float *Op, *t1, *x1, *hp;
    cudaGetSymbolAddress((void**)&Op, g_O);
    cudaGetSymbolAddress((void**)&t1, g_t1);
    cudaGetSymbolAddress((void**)&x1, g_x1);
    cudaGetSymbolAddress((void**)&hp, g_h);

    cudaFuncSetAttribute(gemm_tf32<0,128>,
                         cudaFuncAttributeMaxDynamicSharedMemorySize, GEMM_SMEM_128);
    cudaFuncSetAttribute(gemm_tf32<1,128>,
                         cudaFuncAttributeMaxDynamicSharedMemorySize, GEMM_SMEM_128);
    cudaFuncSetAttribute(gemm_tf32<2,256>,
                         cudaFuncAttributeMaxDynamicSharedMemorySize, GEMM_SMEM_256);
    cudaFuncSetAttribute(attn_kernel,
                         cudaFuncAttributeMaxDynamicSharedMemorySize, ATTN_SMEM);

    // 1. QKV projections (tf32 TC) -> g_Q/g_K/g_V [B,H,T,64]
    gemm_tf32<0,128><<<dim3(8, 32, 3), 256, GEMM_SMEM_128>>>(
        x, Wq, Wk, Wv, nullptr, nullptr, nullptr, MTOT, 1024, 1024);
    // 2. causal attention (tf32 TC) -> g_O [B*T, E]
    attn_kernel<<<dim3(32, 16, 2), 128, ATTN_SMEM>>>(Op);
    // 3. out proj + bias + residual -> t1
    gemm_tf32<1,128><<<dim3(8, 32, 1), 256, GEMM_SMEM_128>>>(
        Op, Wo, nullptr, nullptr, bo, x, t1, MTOT, 1024, 1024);
    // 4. LN1 -> x1
    ln_kernel<<<MTOT, 256>>>(t1, g1, be1, x1);
    // 5. FFN up + relu -> g_h [4096,4096]  (128x256 tiles)
    gemm_tf32<2,256><<<dim3(16, 32, 1), 256, GEMM_SMEM_256>>>(
        x1, W1, nullptr, nullptr, b1, nullptr, hp, MTOT, 4096, 1024);
    // 6. FFN down + bias + residual -> t1
    gemm_tf32<1,128><<<dim3(8, 32, 1), 256, GEMM_SMEM_128>>>(
        hp, W2, nullptr, nullptr, b2, x1, t1, MTOT, 1024, 4096);
    // 7. LN2 -> output
    ln_kernel<<<MTOT, 256>>>(t1, g2, be2, out);
}

// round 11
// speedup vs baseline: 6.0115x; 1.8766x over previous
#include <cuda_runtime.h>
#include <cuda_fp16.h>
#include <cstdint>

// Problem constants
#define BB 2
#define TT 2048
#define EE 1024
#define HH 16
#define DHS 64
#define MTOT (BB*TT)          // 4096 rows

// ---------------- scratch (device globals; no allocation) ----------------
__device__ __half g_xh[MTOT*EE];            // x in fp16
__device__ __half g_Qh[BB*HH*TT*DHS];       // [B,H,T,64] fp16 (pre-scaled 0.125)
__device__ __half g_Kh[BB*HH*TT*DHS];
__device__ __half g_Vh[BB*HH*TT*DHS];
__device__ __half g_Oh[MTOT*EE];            // attention output fp16
__device__ float  g_t1[MTOT*EE];            // pre-LN fp32
__device__ float  g_x1[MTOT*EE];            // post-LN1 fp32 (residual)
__device__ __half g_x1h[MTOT*EE];           // post-LN1 fp16
__device__ __half g_hh[MTOT*4*EE];          // FFN hidden fp16 [4096,4096]
// transposed fp16 weights: [N,K] K-contiguous
__device__ __half g_Wqt[HH*EE*DHS];
__device__ __half g_Wkt[HH*EE*DHS];
__device__ __half g_Wvt[HH*EE*DHS];
__device__ __half g_Wot[EE*EE];
__device__ __half g_W1t[4*EE*EE];
__device__ __half g_W2t[4*EE*EE];

// ---------------- helpers ---------------------------------------------------
__device__ __forceinline__ void mma16(float* c, const unsigned* a, const unsigned* b) {
    asm volatile(
        "mma.sync.aligned.m16n8k16.row.col.f32.f16.f16.f32 "
        "{%0,%1,%2,%3},{%4,%5,%6,%7},{%8,%9},{%0,%1,%2,%3};"
        : "+f"(c[0]), "+f"(c[1]), "+f"(c[2]), "+f"(c[3])
        : "r"(a[0]), "r"(a[1]), "r"(a[2]), "r"(a[3]), "r"(b[0]), "r"(b[1]));
}

__device__ __forceinline__ void cp16s(uint32_t dst, const void* src) {
    asm volatile("cp.async.cg.shared.global [%0], [%1], 16;" :: "r"(dst), "l"(src));
}

__device__ __forceinline__ void ldsm4t(unsigned& r0, unsigned& r1,
                                       unsigned& r2, unsigned& r3, uint32_t addr) {
    asm volatile("ldmatrix.sync.aligned.m8n8.x4.trans.shared.b16 {%0,%1,%2,%3}, [%4];"
                 : "=r"(r0), "=r"(r1), "=r"(r2), "=r"(r3) : "r"(addr));
}

__device__ __forceinline__ uint32_t smem_u32(const void* p) {
    uint32_t a;
    asm("{ .reg .u64 t; cvta.to.shared.u64 t, %1; cvt.u32.u64 %0, t; }"
        : "=r"(a) : "l"(p));
    return a;
}

// ---------------- pre-passes -------------------------------------------------
__global__ __launch_bounds__(256) void cvt_h(const float* __restrict__ in,
                                             __half* __restrict__ out) {
    int i = blockIdx.x * 256 + threadIdx.x;
    float4 v = ((const float4*)in)[i];
    ((__half2*)out)[2 * i]     = __floats2half2_rn(v.x, v.y);
    ((__half2*)out)[2 * i + 1] = __floats2half2_rn(v.z, v.w);
}

// [R,C] fp32 -> [C,R] fp16 (batched over blockIdx.z)
__global__ __launch_bounds__(256) void transpose_cvt(
    const float* __restrict__ in, __half* __restrict__ out, int R, int C)
{
    __shared__ float tl[32][33];
    const float* inp = in + (size_t)blockIdx.z * R * C;
    __half* outp = out + (size_t)blockIdx.z * R * C;
    int c = blockIdx.x * 32 + threadIdx.x;
    int r0 = blockIdx.y * 32 + threadIdx.y;
    #pragma unroll
    for (int j = 0; j < 32; j += 8)
        tl[threadIdx.y + j][threadIdx.x] = inp[(size_t)(r0 + j) * C + c];
    __syncthreads();
    int rr = blockIdx.y * 32 + threadIdx.x;
    int cc = blockIdx.x * 32 + threadIdx.y;
    #pragma unroll
    for (int j = 0; j < 32; j += 8)
        outp[(size_t)(cc + j) * R + rr] = __float2half_rn(tl[threadIdx.x][threadIdx.y + j]);
}

// ---------------- fp16 tensor-core GEMM, 3-stage cp.async -------------------
// C[M,N] = A[M,K] @ Bt[N,K]^T. 128x128 CTA tile, K-tile 64, 256 threads.
// MODE 0: QKV — Bt select by blockIdx.z; fp16 scatter-write Q(*0.125)/K/V
// MODE 1: C(fp32) = A@B + bias + res
// MODE 2: Ch(fp16) = relu(A@B + bias)
#define TILE_B 18432                 // one operand tile: 128*72*2 bytes
#define STAGE_B (2*TILE_B)           // A + B
#define GSMEM (3*STAGE_B)            // 110592 B

template <int MODE>
__global__ __launch_bounds__(256) void gemm_fp16(
    const __half* __restrict__ A,
    const __half* __restrict__ Bt0, const __half* __restrict__ Bt1,
    const __half* __restrict__ Bt2,
    const float* __restrict__ bias, const float* __restrict__ res,
    float* __restrict__ C, __half* __restrict__ Ch, int M, int N, int K)
{
    extern __shared__ __align__(16) char smem_raw[];
    const uint32_t smem_base = smem_u32(smem_raw);

    const int tid  = threadIdx.x;
    const int lane = tid & 31;
    const int g    = lane >> 2;
    const int tg   = lane & 3;
    const int wid  = tid >> 5;
    const int wm   = (wid & 1) * 64;
    const int wn   = (wid >> 1) * 32;
    const int bm   = blockIdx.y * 128;
    const int bn   = blockIdx.x * 128;

    const __half* Bt = Bt0;
    if (MODE == 0) Bt = (blockIdx.z == 0) ? Bt0 : (blockIdx.z == 1) ? Bt1 : Bt2;

    auto issue = [&](int t) {
        const int buf = t % 3;
        const int k0 = t << 6;
        const uint32_t Ab = smem_base + buf * STAGE_B;
        const uint32_t Bb = Ab + TILE_B;
        #pragma unroll
        for (int i = 0; i < 4; i++) {
            int e = tid + i * 256;           // 1024 16B-chunks (128 rows x 8)
            int r = e >> 3, c8 = e & 7;
            cp16s(Ab + r * 144 + c8 * 16, &A[(size_t)(bm + r) * K + k0 + c8 * 8]);
        }
        #pragma unroll
        for (int i = 0; i < 4; i++) {
            int e = tid + i * 256;
            int r = e >> 3, c8 = e & 7;
            cp16s(Bb + r * 144 + c8 * 16, &Bt[(size_t)(bn + r) * K + k0 + c8 * 8]);
        }
        asm volatile("cp.async.commit_group;");
    };

    float acc[4][4][4];
    #pragma unroll
    for (int mi = 0; mi < 4; mi++)
        #pragma unroll
        for (int ni = 0; ni < 4; ni++)
            #pragma unroll
            for (int e = 0; e < 4; e++) acc[mi][ni][e] = 0.0f;

    const int nt = K >> 6;
    issue(0);
    if (nt > 1) issue(1);

    for (int t = 0; t < nt; t++) {
        if (t + 2 < nt) issue(t + 2);       // buffer (t+2)%3 freed at iter t-1
        int rem = nt - 1 - t; if (rem > 2) rem = 2;
        if (rem == 2)      asm volatile("cp.async.wait_group 2;");
        else if (rem == 1) asm volatile("cp.async.wait_group 1;");
        else               asm volatile("cp.async.wait_group 0;");
        __syncthreads();

        const unsigned* Au = (const unsigned*)(smem_raw + (t % 3) * STAGE_B);
        const unsigned* Bu = (const unsigned*)(smem_raw + (t % 3) * STAGE_B + TILE_B);

        #pragma unroll
        for (int ks = 0; ks < 4; ks++) {
            const int kw = ks * 8;           // k word offset (16 fp16 = 8 words)
            unsigned af[4][4];
            #pragma unroll
            for (int mi = 0; mi < 4; mi++) {
                int row = wm + mi * 16;
                af[mi][0] = Au[(row + g) * 36 + kw + tg];
                af[mi][1] = Au[(row + 8 + g) * 36 + kw + tg];
                af[mi][2] = Au[(row + g) * 36 + kw + 4 + tg];
                af[mi][3] = Au[(row + 8 + g) * 36 + kw + 4 + tg];
            }
            unsigned bf[4][2];
            #pragma unroll
            for (int ni = 0; ni < 4; ni++) {
                int col = wn + ni * 8 + g;
                bf[ni][0] = Bu[col * 36 + kw + tg];
                bf[ni][1] = Bu[col * 36 + kw + 4 + tg];
            }
            #pragma unroll
            for (int mi = 0; mi < 4; mi++)
                #pragma unroll
                for (int ni = 0; ni < 4; ni++)
                    mma16(acc[mi][ni], af[mi], bf[ni]);
        }
        __syncthreads();
    }

    // epilogue
    #pragma unroll
    for (int mi = 0; mi < 4; mi++) {
        #pragma unroll
        for (int r2 = 0; r2 < 2; r2++) {
            int m = bm + wm + mi * 16 + g + r2 * 8;
            #pragma unroll
            for (int ni = 0; ni < 4; ni++) {
                int n = bn + wn + ni * 8 + tg * 2;
                float v0 = acc[mi][ni][r2 * 2 + 0];
                float v1 = acc[mi][ni][r2 * 2 + 1];
                if (MODE == 0) {
                    __half* Ob = (blockIdx.z == 0) ? g_Qh : (blockIdx.z == 1) ? g_Kh : g_Vh;
                    if (blockIdx.z == 0) { v0 *= 0.125f; v1 *= 0.125f; }
                    int b = m >> 11, tt2 = m & 2047;
                    int hh = n >> 6, dd = n & 63;
                    *(__half2*)&Ob[(((size_t)(b * HH + hh) * TT + tt2) * DHS) + dd] =
                        __floats2half2_rn(v0, v1);
                } else {
                    v0 += bias[n]; v1 += bias[n + 1];
                    if (MODE == 1) {
                        v0 += res[(size_t)m * N + n];
                        v1 += res[(size_t)m * N + n + 1];
                        C[(size_t)m * N + n]     = v0;
                        C[(size_t)m * N + n + 1] = v1;
                    } else {
                        v0 = fmaxf(v0, 0.0f); v1 = fmaxf(v1, 0.0f);
                        *(__half2*)&Ch[(size_t)m * N + n] = __floats2half2_rn(v0, v1);
                    }
                }
            }
        }
    }
}

// ---------------- fp16 tensor-core causal flash attention -------------------
// grid (T/64=32, H=16, B=2), block 128 (4 warps), warp owns 16 Q rows.
#define ATILE_H 4608                // 64*72 halves per tile
#define ATILE_B (ATILE_H*2)         // 9216 bytes
#define ATTN_SMEM (6*ATILE_B)       // Q + 2K + 2V + P = 55296 B

__global__ __launch_bounds__(128) void attn_kernel(__half* __restrict__ Oh)
{
    extern __shared__ __align__(16) __half sm[];
    __half* Qs = sm;                        // [64][72]
    __half* Ks = sm + ATILE_H;              // [2][64][72]
    __half* Vs = sm + 3 * ATILE_H;          // [2][64][72]
    __half* Ps = sm + 5 * ATILE_H;          // [64][72]
    const uint32_t smem_base = smem_u32(sm);

    const int qt = blockIdx.x, h = blockIdx.y, b = blockIdx.z;
    const int tid = threadIdx.x, wid = tid >> 5, lane = tid & 31;
    const int g = lane >> 2, tg = lane & 3;
    const int wm = wid * 16;
    const size_t base = ((size_t)(b * HH + h)) * TT * DHS;
    const __half* Qg = g_Qh + base;
    const __half* Kg = g_Kh + base;
    const __half* Vg = g_Vh + base;

    auto issue_kv = [&](int kt) {
        uint32_t Kb = smem_base + (1 + (kt & 1)) * ATILE_B;
        uint32_t Vb = smem_base + (3 + (kt & 1)) * ATILE_B;
        #pragma unroll
        for (int i = 0; i < 4; i++) {
            int e = tid + i * 128;           // 512 chunks: 64 rows x 8
            int r = e >> 3, c8 = e & 7;
            cp16s(Kb + r * 144 + c8 * 16, &Kg[(size_t)(kt * 64 + r) * 64 + c8 * 8]);
            cp16s(Vb + r * 144 + c8 * 16, &Vg[(size_t)(kt * 64 + r) * 64 + c8 * 8]);
        }
        asm volatile("cp.async.commit_group;");
    };

    // Q tile (already scaled by 0.125 at QKV write) — same commit group as KV0
    #pragma unroll
    for (int i = 0; i < 4; i++) {
        int e = tid + i * 128;
        int r = e >> 3, c8 = e & 7;
        cp16s(smem_base + r * 144 + c8 * 16, &Qg[(size_t)(qt * 64 + r) * 64 + c8 * 8]);
    }
    issue_kv(0);

    float m_i[2] = {-1e30f, -1e30f}, l_i[2] = {0.0f, 0.0f};
    float o[8][4];
    #pragma unroll
    for (int ni = 0; ni < 8; ni++)
        #pragma unroll
        for (int e = 0; e < 4; e++) o[ni][e] = 0.0f;

    const unsigned* Qu = (const unsigned*)Qs;
    const unsigned* Pu = (const unsigned*)Ps;

    for (int kt = 0; kt <= qt; kt++) {
        __syncthreads();                     // buffer (kt+1)&1 free to overwrite
        if (kt + 1 <= qt) {
            issue_kv(kt + 1);
            asm volatile("cp.async.wait_group 1;");
        } else {
            asm volatile("cp.async.wait_group 0;");
        }
        __syncthreads();
        const unsigned* Ku = (const unsigned*)(Ks + (kt & 1) * ATILE_H);
        const uint32_t Vb = smem_base + (3 + (kt & 1)) * ATILE_B;

        // S = Q K^T  (warp: 16 rows x 64 cols), K is [n][k] -> direct lds
        float s[8][4] = {};
        #pragma unroll
        for (int ks = 0; ks < 4; ks++) {
            const int kw = ks * 8;
            unsigned aq[4];
            aq[0] = Qu[(wm + g) * 36 + kw + tg];
            aq[1] = Qu[(wm + 8 + g) * 36 + kw + tg];
            aq[2] = Qu[(wm + g) * 36 + kw + 4 + tg];
            aq[3] = Qu[(wm + 8 + g) * 36 + kw + 4 + tg];
            #pragma unroll
            for (int ni = 0; ni < 8; ni++) {
                unsigned bk[2];
                bk[0] = Ku[(ni * 8 + g) * 36 + kw + tg];
                bk[1] = Ku[(ni * 8 + g) * 36 + kw + 4 + tg];
                mma16(s[ni], aq, bk);
            }
        }
        if (kt == qt) {
            #pragma unroll
            for (int ni = 0; ni < 8; ni++)
                #pragma unroll
                for (int e = 0; e < 4; e++) {
                    int row = wm + g + ((e >= 2) ? 8 : 0);
                    int col = ni * 8 + tg * 2 + (e & 1);
                    if (col > row) s[ni][e] = -1e30f;
                }
        }
        // online softmax (rows g and g+8; quad lanes share a row)
        #pragma unroll
        for (int r2 = 0; r2 < 2; r2++) {
            float rm = -1e30f;
            #pragma unroll
            for (int ni = 0; ni < 8; ni++) {
                rm = fmaxf(rm, s[ni][2 * r2]);
                rm = fmaxf(rm, s[ni][2 * r2 + 1]);
            }
            rm = fmaxf(rm, __shfl_xor_sync(0xffffffffu, rm, 1));
            rm = fmaxf(rm, __shfl_xor_sync(0xffffffffu, rm, 2));
            float mn = fmaxf(m_i[r2], rm);
            float alpha = __expf(m_i[r2] - mn);
            m_i[r2] = mn;
            float rs = 0.0f;
            #pragma unroll
            for (int ni = 0; ni < 8; ni++) {
                float p0 = __expf(s[ni][2 * r2] - mn);
                float p1 = __expf(s[ni][2 * r2 + 1] - mn);
                s[ni][2 * r2] = p0; s[ni][2 * r2 + 1] = p1;
                rs += p0 + p1;
            }
            rs += __shfl_xor_sync(0xffffffffu, rs, 1);
            rs += __shfl_xor_sync(0xffffffffu, rs, 2);
            l_i[r2] = l_i[r2] * alpha + rs;
            #pragma unroll
            for (int ni = 0; ni < 8; ni++) {
                o[ni][2 * r2] *= alpha;
                o[ni][2 * r2 + 1] *= alpha;
            }
        }
        // store P fp16 (warp-private rows)
        __half2* Pw = (__half2*)Ps;
        #pragma unroll
        for (int ni = 0; ni < 8; ni++) {
            Pw[(wm + g) * 36 + ni * 4 + tg]     = __floats2half2_rn(s[ni][0], s[ni][1]);
            Pw[(wm + 8 + g) * 36 + ni * 4 + tg] = __floats2half2_rn(s[ni][2], s[ni][3]);
        }
        __syncwarp();
        // O += P V ; V is [s][d] -> B frags via ldmatrix.x4.trans
        #pragma unroll
        for (int ks = 0; ks < 4; ks++) {
            const int kw = ks * 8;
            unsigned ap[4];
            ap[0] = Pu[(wm + g) * 36 + kw + tg];
            ap[1] = Pu[(wm + 8 + g) * 36 + kw + tg];
            ap[2] = Pu[(wm + g) * 36 + kw + 4 + tg];
            ap[3] = Pu[(wm + 8 + g) * 36 + kw + 4 + tg];
            #pragma unroll
            for (int ni2 = 0; ni2 < 4; ni2++) {
                int row = ks * 16 + (lane & 15);
                int n0 = ni2 * 16 + ((lane >> 4) << 3);
                unsigned r0, r1, r2, r3;
                ldsm4t(r0, r1, r2, r3, Vb + row * 144 + n0 * 2);
                unsigned bv0[2] = {r0, r1};
                unsigned bv1[2] = {r2, r3};
                mma16(o[2 * ni2], ap, bv0);
                mma16(o[2 * ni2 + 1], ap, bv1);
            }
        }
    }

    // epilogue: Oh[(b*T + t)*E + h*64 + col] fp16
    const float inv0 = 1.0f / l_i[0], inv1 = 1.0f / l_i[1];
    #pragma unroll
    for (int ni = 0; ni < 8; ni++) {
        int t0 = qt * 64 + wm + g;
        int col = h * 64 + ni * 8 + tg * 2;
        *(__half2*)&Oh[((size_t)(b * TT + t0)) * EE + col] =
            __floats2half2_rn(o[ni][0] * inv0, o[ni][1] * inv0);
        *(__half2*)&Oh[((size_t)(b * TT + t0 + 8)) * EE + col] =
            __floats2half2_rn(o[ni][2] * inv1, o[ni][3] * inv1);
    }
}

// ---------------- LayerNorm over last dim (1024), one block per row --------
__global__ __launch_bounds__(256) void ln_kernel(
    const float* __restrict__ in, const float* __restrict__ g,
    const float* __restrict__ be, float* __restrict__ out,
    __half* __restrict__ outh)
{
    const int row = blockIdx.x;
    const int tid = threadIdx.x;
    const float4* p = (const float4*)(in + (size_t)row * EE);
    float4 x = p[tid];
    float s  = x.x + x.y + x.z + x.w;
    float ss = x.x * x.x + x.y * x.y + x.z * x.z + x.w * x.w;
    #pragma unroll
    for (int off = 16; off >= 1; off >>= 1) {
        s  += __shfl_xor_sync(0xffffffffu, s,  off);
        ss += __shfl_xor_sync(0xffffffffu, ss, off);
    }
    __shared__ float ws[8], wss[8];
    int w = tid >> 5, ln = tid & 31;
    if (ln == 0) { ws[w] = s; wss[w] = ss; }
    __syncthreads();
    s = 0.0f; ss = 0.0f;
    #pragma unroll
    for (int i = 0; i < 8; i++) { s += ws[i]; ss += wss[i]; }
    const float mu  = s * (1.0f / EE);
    const float var = ss * (1.0f / EE) - mu * mu;
    const float rs  = rsqrtf(var + 1e-5f);
    float4 gg = ((const float4*)g)[tid];
    float4 bb = ((const float4*)be)[tid];
    float4 y;
    y.x = (x.x - mu) * rs * gg.x + bb.x;
    y.y = (x.y - mu) * rs * gg.y + bb.y;
    y.z = (x.z - mu) * rs * gg.z + bb.z;
    y.w = (x.w - mu) * rs * gg.w + bb.w;
    ((float4*)(out + (size_t)row * EE))[tid] = y;
    if (outh) {
        __half2* oh = (__half2*)(outh + (size_t)row * EE);
        oh[2 * tid]     = __floats2half2_rn(y.x, y.y);
        oh[2 * tid + 1] = __floats2half2_rn(y.z, y.w);
    }
}

// ---------------- launch ----------------------------------------------------
extern "C" void kernel_launch(void* const* d_in, const int* in_sizes, int n_in,
                              void* d_out, int out_size)
{
    const float* x   = (const float*)d_in[0];
    const float* Wq  = (const float*)d_in[1];
    const float* Wk  = (const float*)d_in[2];
    const float* Wv  = (const float*)d_in[3];
    const float* Wo  = (const float*)d_in[4];
    const float* bo  = (const float*)d_in[5];
    const float* W1  = (const float*)d_in[6];
    const float* b1  = (const float*)d_in[7];
    const float* W2  = (const float*)d_in[8];
    const float* b2  = (const float*)d_in[9];
    const float* g1  = (const float*)d_in[10];
    const float* be1 = (const float*)d_in[11];
    const float* g2  = (const float*)d_in[12];
    const float* be2 = (const float*)d_in[13];
    float* out = (float*)d_out;

    __half *xh, *Ohp, *x1h, *hh;
    __half *wqt, *wkt, *wvt, *wot, *w1t, *w2t;
    float *t1, *x1;
    cudaGetSymbolAddress((void**)&xh,  g_xh);
    cudaGetSymbolAddress((void**)&Ohp, g_Oh);
    cudaGetSymbolAddress((void**)&t1,  g_t1);
    cudaGetSymbolAddress((void**)&x1,  g_x1);
    cudaGetSymbolAddress((void**)&x1h, g_x1h);
    cudaGetSymbolAddress((void**)&hh,  g_hh);
    cudaGetSymbolAddress((void**)&wqt, g_Wqt);
    cudaGetSymbolAddress((void**)&wkt, g_Wkt);
    cudaGetSymbolAddress((void**)&wvt, g_Wvt);
    cudaGetSymbolAddress((void**)&wot, g_Wot);
    cudaGetSymbolAddress((void**)&w1t, g_W1t);
    cudaGetSymbolAddress((void**)&w2t, g_W2t);

    cudaFuncSetAttribute(gemm_fp16<0>,
                         cudaFuncAttributeMaxDynamicSharedMemorySize, GSMEM);
    cudaFuncSetAttribute(gemm_fp16<1>,
                         cudaFuncAttributeMaxDynamicSharedMemorySize, GSMEM);
    cudaFuncSetAttribute(gemm_fp16<2>,
                         cudaFuncAttributeMaxDynamicSharedMemorySize, GSMEM);
    cudaFuncSetAttribute(attn_kernel,
                         cudaFuncAttributeMaxDynamicSharedMemorySize, ATTN_SMEM);

    dim3 tb(32, 8);
    // 0. fp16 conversions / weight transposes
    cvt_h<<<MTOT*EE/1024, 256>>>(x, xh);
    transpose_cvt<<<dim3(2, 32, 16), tb>>>(Wq, wqt, 1024, 64);
    transpose_cvt<<<dim3(2, 32, 16), tb>>>(Wk, wkt, 1024, 64);
    transpose_cvt<<<dim3(2, 32, 16), tb>>>(Wv, wvt, 1024, 64);
    transpose_cvt<<<dim3(32, 32, 1), tb>>>(Wo, wot, 1024, 1024);
    transpose_cvt<<<dim3(128, 32, 1), tb>>>(W1, w1t, 1024, 4096);
    transpose_cvt<<<dim3(32, 128, 1), tb>>>(W2, w2t, 4096, 1024);

    // 1. QKV projections -> fp16 Q(*0.125)/K/V [B,H,T,64]
    gemm_fp16<0><<<dim3(8, 32, 3), 256, GSMEM>>>(
        xh, wqt, wkt, wvt, nullptr, nullptr, nullptr, nullptr, MTOT, 1024, 1024);
    // 2. causal attention -> fp16 O [B*T, E]
    attn_kernel<<<dim3(32, 16, 2), 128, ATTN_SMEM>>>(Ohp);
    // 3. out proj + bias + residual -> t1 (fp32)
    gemm_fp16<1><<<dim3(8, 32, 1), 256, GSMEM>>>(
        Ohp, wot, nullptr, nullptr, bo, x, t1, nullptr, MTOT, 1024, 1024);
    // 4. LN1 -> x1 (fp32) + x1h (fp16)
    ln_kernel<<<MTOT, 256>>>(t1, g1, be1, x1, x1h);
    // 5. FFN up + relu -> hh (fp16) [4096,4096]
    gemm_fp16<2><<<dim3(32, 32, 1), 256, GSMEM>>>(
        x1h, w1t, nullptr, nullptr, b1, nullptr, nullptr, hh, MTOT, 4096, 1024);
    // 6. FFN down + bias + residual -> t1 (fp32)
    gemm_fp16<1><<<dim3(8, 32, 1), 256, GSMEM>>>(
        hh, w2t, nullptr, nullptr, b2, x1, t1, nullptr, MTOT, 1024, 4096);
    // 7. LN2 -> output
    ln_kernel<<<MTOT, 256>>>(t1, g2, be2, out, nullptr);
}

// round 14
// speedup vs baseline: 6.4123x; 1.0667x over previous
#include <cuda_runtime.h>
#include <cuda_fp16.h>
#include <cstdint>

// Problem constants
#define BB 2
#define TT 2048
#define EE 1024
#define HH 16
#define DHS 64
#define MTOT (BB*TT)          // 4096 rows

// ---------------- scratch (device globals; no allocation) ----------------
__device__ __half g_xh[MTOT*EE];            // x in fp16
__device__ __half g_Qh[BB*HH*TT*DHS];       // [B,H,T,64] fp16 (pre-scaled 0.125)
__device__ __half g_Kh[BB*HH*TT*DHS];
__device__ __half g_Vh[BB*HH*TT*DHS];
__device__ __half g_Oh[MTOT*EE];            // attention output fp16
__device__ float  g_t1[MTOT*EE];            // pre-LN fp32
__device__ float  g_x1[MTOT*EE];            // post-LN1 fp32 (residual)
__device__ __half g_x1h[MTOT*EE];           // post-LN1 fp16
__device__ __half g_hh[MTOT*4*EE];          // FFN hidden fp16 [4096,4096]
// fp16 weights in ORIGINAL layout ([K,N]-style; consumed via ldmatrix.trans)
__device__ __half g_Wqh[HH*EE*DHS];
__device__ __half g_Wkh[HH*EE*DHS];
__device__ __half g_Wvh[HH*EE*DHS];
__device__ __half g_Woh[EE*EE];
__device__ __half g_W1h[4*EE*EE];
__device__ __half g_W2h[4*EE*EE];

// ---------------- helpers ---------------------------------------------------
__device__ __forceinline__ void mma16(float* c, const unsigned* a, const unsigned* b) {
    asm volatile(
        "mma.sync.aligned.m16n8k16.row.col.f32.f16.f16.f32 "
        "{%0,%1,%2,%3},{%4,%5,%6,%7},{%8,%9},{%0,%1,%2,%3};"
        : "+f"(c[0]), "+f"(c[1]), "+f"(c[2]), "+f"(c[3])
        : "r"(a[0]), "r"(a[1]), "r"(a[2]), "r"(a[3]), "r"(b[0]), "r"(b[1]));
}

__device__ __forceinline__ void cp16s(uint32_t dst, const void* src) {
    asm volatile("cp.async.cg.shared.global [%0], [%1], 16;" :: "r"(dst), "l"(src));
}

__device__ __forceinline__ void ldsm4(unsigned& r0, unsigned& r1,
                                      unsigned& r2, unsigned& r3, uint32_t addr) {
    asm volatile("ldmatrix.sync.aligned.m8n8.x4.shared.b16 {%0,%1,%2,%3}, [%4];"
                 : "=r"(r0), "=r"(r1), "=r"(r2), "=r"(r3) : "r"(addr));
}

__device__ __forceinline__ void ldsm4t(unsigned& r0, unsigned& r1,
                                       unsigned& r2, unsigned& r3, uint32_t addr) {
    asm volatile("ldmatrix.sync.aligned.m8n8.x4.trans.shared.b16 {%0,%1,%2,%3}, [%4];"
                 : "=r"(r0), "=r"(r1), "=r"(r2), "=r"(r3) : "r"(addr));
}

__device__ __forceinline__ uint32_t smem_u32(const void* p) {
    uint32_t a;
    asm("{ .reg .u64 t; cvta.to.shared.u64 t, %1; cvt.u32.u64 %0, t; }"
        : "=r"(a) : "l"(p));
    return a;
}

// ---------------- pre-pass: fp32 -> fp16 streaming convert ------------------
__global__ __launch_bounds__(256) void cvt_h(const float* __restrict__ in,
                                             __half* __restrict__ out) {
    int i = blockIdx.x * 256 + threadIdx.x;
    float4 v = ((const float4*)in)[i];
    ((__half2*)out)[2 * i]     = __floats2half2_rn(v.x, v.y);
    ((__half2*)out)[2 * i + 1] = __floats2half2_rn(v.z, v.w);
}

// ---------------- fp16 tensor-core GEMM, 3-stage cp.async, ldmatrix --------
// C[M,N] = A[M,K] @ B[K,N] (+ epilogue). 128x128 CTA tile, K-tile 64, 256 thr.
// A smem: [128][72] halves (row 144 B). B smem: [64][136] halves (row 272 B),
// native [k][n] layout consumed via ldmatrix.x4.trans.
// MODE 0: QKV — B select by blockIdx.z from W[H,E,HS]; fp16 scatter-write
// MODE 1: C(fp32) = A@B + bias + res
// MODE 2: Ch(fp16) = relu(A@B + bias)
#define ATILE_BYTES 18432            // 128*144
#define BTILE_BYTES 17408            // 64*272
#define STAGE_B (ATILE_BYTES + BTILE_BYTES)
#define GSMEM (3*STAGE_B)            // 107520 B

template <int MODE>
__global__ __launch_bounds__(256) void gemm_fp16(
    const __half* __restrict__ A,
    const __half* __restrict__ B0, const __half* __restrict__ B1,
    const __half* __restrict__ B2,
    const float* __restrict__ bias, const float* __restrict__ res,
    float* __restrict__ C, __half* __restrict__ Ch, int M, int N, int K)
{
    extern __shared__ __align__(16) char smem_raw[];
    const uint32_t smem_base = smem_u32(smem_raw);

    const int tid  = threadIdx.x;
    const int lane = tid & 31;
    const int g    = lane >> 2;
    const int tg   = lane & 3;
    const int wid  = tid >> 5;
    const int wm   = (wid & 1) * 64;
    const int wn   = (wid >> 1) * 32;
    const int bm   = blockIdx.y * 128;
    const int bn   = blockIdx.x * 128;

    const __half* Bw = B0;
    if (MODE == 0) Bw = (blockIdx.z == 0) ? B0 : (blockIdx.z == 1) ? B1 : B2;

    // ldmatrix lane-derived address components
    const int l15 = lane & 15;
    const int lhi = (lane >> 4) << 3;     // 0 or 8

    auto issue = [&](int t) {
        const int buf = t % 3;
        const int k0 = t << 6;
        const uint32_t Ab = smem_base + buf * STAGE_B;
        const uint32_t Bb = Ab + ATILE_BYTES;
        #pragma unroll
        for (int i = 0; i < 4; i++) {
            int e = tid + i * 256;           // A: 128 rows x 8 chunks
            int r = e >> 3, c8 = e & 7;
            cp16s(Ab + r * 144 + c8 * 16, &A[(size_t)(bm + r) * K + k0 + c8 * 8]);
        }
        #pragma unroll
        for (int i = 0; i < 4; i++) {
            int e = tid + i * 256;           // B: 64 k-rows x 16 chunks
            int r = e >> 4, c8 = e & 15;
            const __half* src;
            if (MODE == 0) {
                int n0 = bn + c8 * 8;
                src = &Bw[(size_t)(n0 >> 6) * (EE * DHS) + (size_t)(k0 + r) * 64 + (n0 & 63)];
            } else {
                src = &Bw[(size_t)(k0 + r) * N + bn + c8 * 8];
            }
            cp16s(Bb + r * 272 + c8 * 16, src);
        }
        asm volatile("cp.async.commit_group;");
    };

    float acc[4][4][4];
    #pragma unroll
    for (int mi = 0; mi < 4; mi++)
        #pragma unroll
        for (int ni = 0; ni < 4; ni++)
            #pragma unroll
            for (int e = 0; e < 4; e++) acc[mi][ni][e] = 0.0f;

    const int nt = K >> 6;
    issue(0);
    if (nt > 1) issue(1);

    for (int t = 0; t < nt; t++) {
        if (t + 2 < nt) issue(t + 2);
        int rem = nt - 1 - t; if (rem > 2) rem = 2;
        if (rem == 2)      asm volatile("cp.async.wait_group 2;");
        else if (rem == 1) asm volatile("cp.async.wait_group 1;");
        else               asm volatile("cp.async.wait_group 0;");
        __syncthreads();

        const uint32_t Ab = smem_base + (t % 3) * STAGE_B;
        const uint32_t Bb = Ab + ATILE_BYTES;

        #pragma unroll
        for (int ks = 0; ks < 4; ks++) {
            // A fragments: 4x ldmatrix.x4 (rows wm+mi*16+l15, k halves ks*16+lhi)
            unsigned af[4][4];
            #pragma unroll
            for (int mi = 0; mi < 4; mi++) {
                int row = wm + mi * 16 + l15;
                ldsm4(af[mi][0], af[mi][1], af[mi][2], af[mi][3],
                      Ab + row * 144 + (ks * 16 + lhi) * 2);
            }
            // B fragments: 2x ldmatrix.x4.trans (k rows ks*16+l15, n cols)
            #pragma unroll
            for (int ni2 = 0; ni2 < 2; ni2++) {
                int krow = ks * 16 + l15;
                int n0 = wn + ni2 * 16 + lhi;
                unsigned r0, r1, r2, r3;
                ldsm4t(r0, r1, r2, r3, Bb + krow * 272 + n0 * 2);
                unsigned bv0[2] = {r0, r1};
                unsigned bv1[2] = {r2, r3};
                #pragma unroll
                for (int mi = 0; mi < 4; mi++) {
                    mma16(acc[mi][2 * ni2],     af[mi], bv0);
                    mma16(acc[mi][2 * ni2 + 1], af[mi], bv1);
                }
            }
        }
        __syncthreads();
    }

    // epilogue
    #pragma unroll
    for (int mi = 0; mi < 4; mi++) {
        #pragma unroll
        for (int r2 = 0; r2 < 2; r2++) {
            int m = bm + wm + mi * 16 + g + r2 * 8;
            #pragma unroll
            for (int ni = 0; ni < 4; ni++) {
                int n = bn + wn + ni * 8 + tg * 2;
                float v0 = acc[mi][ni][r2 * 2 + 0];
                float v1 = acc[mi][ni][r2 * 2 + 1];
                if (MODE == 0) {
                    __half* Ob = (blockIdx.z == 0) ? g_Qh : (blockIdx.z == 1) ? g_Kh : g_Vh;
                    if (blockIdx.z == 0) { v0 *= 0.125f; v1 *= 0.125f; }
                    int b = m >> 11, tt2 = m & 2047;
                    int hh = n >> 6, dd = n & 63;
                    *(__half2*)&Ob[(((size_t)(b * HH + hh) * TT + tt2) * DHS) + dd] =
                        __floats2half2_rn(v0, v1);
                } else {
                    v0 += bias[n]; v1 += bias[n + 1];
                    if (MODE == 1) {
                        v0 += res[(size_t)m * N + n];
                        v1 += res[(size_t)m * N + n + 1];
                        C[(size_t)m * N + n]     = v0;
                        C[(size_t)m * N + n + 1] = v1;
                    } else {
                        v0 = fmaxf(v0, 0.0f); v1 = fmaxf(v1, 0.0f);
                        *(__half2*)&Ch[(size_t)m * N + n] = __floats2half2_rn(v0, v1);
                    }
                }
            }
        }
    }
}

// ---------------- fp16 tensor-core causal flash attention -------------------
// grid (T/64=32, H=16, B=2), block 128 (4 warps), warp owns 16 Q rows.
#define ATILE_H 4608                // 64*72 halves per tile
#define ATILE_B (ATILE_H*2)         // 9216 bytes
#define ATTN_SMEM (6*ATILE_B)       // Q + 2K + 2V + P = 55296 B

__global__ __launch_bounds__(128) void attn_kernel(__half* __restrict__ Oh)
{
    extern __shared__ __align__(16) __half sm[];
    __half* Qs = sm;                        // [64][72]
    __half* Ks = sm + ATILE_H;              // [2][64][72]
    __half* Ps = sm + 5 * ATILE_H;          // [64][72]
    const uint32_t smem_base = smem_u32(sm);

    const int qt = blockIdx.x, h = blockIdx.y, b = blockIdx.z;
    const int tid = threadIdx.x, wid = tid >> 5, lane = tid & 31;
    const int g = lane >> 2, tg = lane & 3;
    const int wm = wid * 16;
    const size_t base = ((size_t)(b * HH + h)) * TT * DHS;
    const __half* Qg = g_Qh + base;
    const __half* Kg = g_Kh + base;
    const __half* Vg = g_Vh + base;

    auto issue_kv = [&](int kt) {
        uint32_t Kb = smem_base + (1 + (kt & 1)) * ATILE_B;
        uint32_t Vb = smem_base + (3 + (kt & 1)) * ATILE_B;
        #pragma unroll
        for (int i = 0; i < 4; i++) {
            int e = tid + i * 128;
            int r = e >> 3, c8 = e & 7;
            cp16s(Kb + r * 144 + c8 * 16, &Kg[(size_t)(kt * 64 + r) * 64 + c8 * 8]);
            cp16s(Vb + r * 144 + c8 * 16, &Vg[(size_t)(kt * 64 + r) * 64 + c8 * 8]);
        }
        asm volatile("cp.async.commit_group;");
    };

    #pragma unroll
    for (int i = 0; i < 4; i++) {
        int e = tid + i * 128;
        int r = e >> 3, c8 = e & 7;
        cp16s(smem_base + r * 144 + c8 * 16, &Qg[(size_t)(qt * 64 + r) * 64 + c8 * 8]);
    }
    issue_kv(0);

    float m_i[2] = {-1e30f, -1e30f}, l_i[2] = {0.0f, 0.0f};
    float o[8][4];
    #pragma unroll
    for (int ni = 0; ni < 8; ni++)
        #pragma unroll
        for (int e = 0; e < 4; e++) o[ni][e] = 0.0f;

    const unsigned* Qu = (const unsigned*)Qs;
    const unsigned* Pu = (const unsigned*)Ps;

    for (int kt = 0; kt <= qt; kt++) {
        __syncthreads();
        if (kt + 1 <= qt) {
            issue_kv(kt + 1);
            asm volatile("cp.async.wait_group 1;");
        } else {
            asm volatile("cp.async.wait_group 0;");
        }
        __syncthreads();
        const unsigned* Ku = (const unsigned*)(Ks + (kt & 1) * ATILE_H);
        const uint32_t Vb = smem_base + (3 + (kt & 1)) * ATILE_B;

        // S = Q K^T
        float s[8][4] = {};
        #pragma unroll
        for (int ks = 0; ks < 4; ks++) {
            const int kw = ks * 8;
            unsigned aq[4];
            aq[0] = Qu[(wm + g) * 36 + kw + tg];
            aq[1] = Qu[(wm + 8 + g) * 36 + kw + tg];
            aq[2] = Qu[(wm + g) * 36 + kw + 4 + tg];
            aq[3] = Qu[(wm + 8 + g) * 36 + kw + 4 + tg];
            #pragma unroll
            for (int ni = 0; ni < 8; ni++) {
                unsigned bk[2];
                bk[0] = Ku[(ni * 8 + g) * 36 + kw + tg];
                bk[1] = Ku[(ni * 8 + g) * 36 + kw + 4 + tg];
                mma16(s[ni], aq, bk);
            }
        }
        if (kt == qt) {
            #pragma unroll
            for (int ni = 0; ni < 8; ni++)
                #pragma unroll
                for (int e = 0; e < 4; e++) {
                    int row = wm + g + ((e >= 2) ? 8 : 0);
                    int col = ni * 8 + tg * 2 + (e & 1);
                    if (col > row) s[ni][e] = -1e30f;
                }
        }
        // online softmax
        #pragma unroll
        for (int r2 = 0; r2 < 2; r2++) {
            float rm = -1e30f;
            #pragma unroll
            for (int ni = 0; ni < 8; ni++) {
                rm = fmaxf(rm, s[ni][2 * r2]);
                rm = fmaxf(rm, s[ni][2 * r2 + 1]);
            }
            rm = fmaxf(rm, __shfl_xor_sync(0xffffffffu, rm, 1));
            rm = fmaxf(rm, __shfl_xor_sync(0xffffffffu, rm, 2));
            float mn = fmaxf(m_i[r2], rm);
            float alpha = __expf(m_i[r2] - mn);
            m_i[r2] = mn;
            float rs = 0.0f;
            #pragma unroll
            for (int ni = 0; ni < 8; ni++) {
                float p0 = __expf(s[ni][2 * r2] - mn);
                float p1 = __expf(s[ni][2 * r2 + 1] - mn);
                s[ni][2 * r2] = p0; s[ni][2 * r2 + 1] = p1;
                rs += p0 + p1;
            }
            rs += __shfl_xor_sync(0xffffffffu, rs, 1);
            rs += __shfl_xor_sync(0xffffffffu, rs, 2);
            l_i[r2] = l_i[r2] * alpha + rs;
            #pragma unroll
            for (int ni = 0; ni < 8; ni++) {
                o[ni][2 * r2] *= alpha;
                o[ni][2 * r2 + 1] *= alpha;
            }
        }
        // store P fp16 (warp-private rows)
        __half2* Pw = (__half2*)Ps;
        #pragma unroll
        for (int ni = 0; ni < 8; ni++) {
            Pw[(wm + g) * 36 + ni * 4 + tg]     = __floats2half2_rn(s[ni][0], s[ni][1]);
            Pw[(wm + 8 + g) * 36 + ni * 4 + tg] = __floats2half2_rn(s[ni][2], s[ni][3]);
        }
        __syncwarp();
        // O += P V
        #pragma unroll
        for (int ks = 0; ks < 4; ks++) {
            const int kw = ks * 8;
            unsigned ap[4];
            ap[0] = Pu[(wm + g) * 36 + kw + tg];
            ap[1] = Pu[(wm + 8 + g) * 36 + kw + tg];
            ap[2] = Pu[(wm + g) * 36 + kw + 4 + tg];
            ap[3] = Pu[(wm + 8 + g) * 36 + kw + 4 + tg];
            #pragma unroll
            for (int ni2 = 0; ni2 < 4; ni2++) {
                int row = ks * 16 + (lane & 15);
                int n0 = ni2 * 16 + ((lane >> 4) << 3);
                unsigned r0, r1, r2, r3;
                ldsm4t(r0, r1, r2, r3, Vb + row * 144 + n0 * 2);
                unsigned bv0[2] = {r0, r1};
                unsigned bv1[2] = {r2, r3};
                mma16(o[2 * ni2], ap, bv0);
                mma16(o[2 * ni2 + 1], ap, bv1);
            }
        }
    }

    const float inv0 = 1.0f / l_i[0], inv1 = 1.0f / l_i[1];
    #pragma unroll
    for (int ni = 0; ni < 8; ni++) {
        int t0 = qt * 64 + wm + g;
        int col = h * 64 + ni * 8 + tg * 2;
        *(__half2*)&Oh[((size_t)(b * TT + t0)) * EE + col] =
            __floats2half2_rn(o[ni][0] * inv0, o[ni][1] * inv0);
        *(__half2*)&Oh[((size_t)(b * TT + t0 + 8)) * EE + col] =
            __floats2half2_rn(o[ni][2] * inv1, o[ni][3] * inv1);
    }
}

// ---------------- LayerNorm over last dim (1024), one block per row --------
__global__ __launch_bounds__(256) void ln_kernel(
    const float* __restrict__ in, const float* __restrict__ g,
    const float* __restrict__ be, float* __restrict__ out,
    __half* __restrict__ outh)
{
    const int row = blockIdx.x;
    const int tid = threadIdx.x;
    const float4* p = (const float4*)(in + (size_t)row * EE);
    float4 x = p[tid];
    float s  = x.x + x.y + x.z + x.w;
    float ss = x.x * x.x + x.y * x.y + x.z * x.z + x.w * x.w;
    #pragma unroll
    for (int off = 16; off >= 1; off >>= 1) {
        s  += __shfl_xor_sync(0xffffffffu, s,  off);
        ss += __shfl_xor_sync(0xffffffffu, ss, off);
    }
    __shared__ float ws[8], wss[8];
    int w = tid >> 5, ln = tid & 31;
    if (ln == 0) { ws[w] = s; wss[w] = ss; }
    __syncthreads();
    s = 0.0f; ss = 0.0f;
    #pragma unroll
    for (int i = 0; i < 8; i++) { s += ws[i]; ss += wss[i]; }
    const float mu  = s * (1.0f / EE);
    const float var = ss * (1.0f / EE) - mu * mu;
    const float rs  = rsqrtf(var + 1e-5f);
    float4 gg = ((const float4*)g)[tid];
    float4 bb = ((const float4*)be)[tid];
    float4 y;
    y.x = (x.x - mu) * rs * gg.x + bb.x;
    y.y = (x.y - mu) * rs * gg.y + bb.y;
    y.z = (x.z - mu) * rs * gg.z + bb.z;
    y.w = (x.w - mu) * rs * gg.w + bb.w;
    ((float4*)(out + (size_t)row * EE))[tid] = y;
    if (outh) {
        __half2* oh = (__half2*)(outh + (size_t)row * EE);
        oh[2 * tid]     = __floats2half2_rn(y.x, y.y);
        oh[2 * tid + 1] = __floats2half2_rn(y.z, y.w);
    }
}

// ---------------- launch ----------------------------------------------------
extern "C" void kernel_launch(void* const* d_in, const int* in_sizes, int n_in,
                              void* d_out, int out_size)
{
    const float* x   = (const float*)d_in[0];
    const float* Wq  = (const float*)d_in[1];
    const float* Wk  = (const float*)d_in[2];
    const float* Wv  = (const float*)d_in[3];
    const float* Wo  = (const float*)d_in[4];
    const float* bo  = (const float*)d_in[5];
    const float* W1  = (const float*)d_in[6];
    const float* b1  = (const float*)d_in[7];
    const float* W2  = (const float*)d_in[8];
    const float* b2  = (const float*)d_in[9];
    const float* g1  = (const float*)d_in[10];
    const float* be1 = (const float*)d_in[11];
    const float* g2  = (const float*)d_in[12];
    const float* be2 = (const float*)d_in[13];
    float* out = (float*)d_out;

    __half *xh, *Ohp, *x1h, *hh;
    __half *wqh, *wkh, *wvh, *woh, *w1h, *w2h;
    float *t1, *x1;
    cudaGetSymbolAddress((void**)&xh,  g_xh);
    cudaGetSymbolAddress((void**)&Ohp, g_Oh);
    cudaGetSymbolAddress((void**)&t1,  g_t1);
    cudaGetSymbolAddress((void**)&x1,  g_x1);
    cudaGetSymbolAddress((void**)&x1h, g_x1h);
    cudaGetSymbolAddress((void**)&hh,  g_hh);
    cudaGetSymbolAddress((void**)&wqh, g_Wqh);
    cudaGetSymbolAddress((void**)&wkh, g_Wkh);
    cudaGetSymbolAddress((void**)&wvh, g_Wvh);
    cudaGetSymbolAddress((void**)&woh, g_Woh);
    cudaGetSymbolAddress((void**)&w1h, g_W1h);
    cudaGetSymbolAddress((void**)&w2h, g_W2h);

    cudaFuncSetAttribute(gemm_fp16<0>,
                         cudaFuncAttributeMaxDynamicSharedMemorySize, GSMEM);
    cudaFuncSetAttribute(gemm_fp16<1>,
                         cudaFuncAttributeMaxDynamicSharedMemorySize, GSMEM);
    cudaFuncSetAttribute(gemm_fp16<2>,
                         cudaFuncAttributeMaxDynamicSharedMemorySize, GSMEM);
    cudaFuncSetAttribute(attn_kernel,
                         cudaFuncAttributeMaxDynamicSharedMemorySize, ATTN_SMEM);

    // 0. fp32 -> fp16 streaming converts (layouts unchanged)
    cvt_h<<<MTOT*EE/1024, 256>>>(x, xh);
    cvt_h<<<HH*EE*DHS/1024, 256>>>(Wq, wqh);
    cvt_h<<<HH*EE*DHS/1024, 256>>>(Wk, wkh);
    cvt_h<<<HH*EE*DHS/1024, 256>>>(Wv, wvh);
    cvt_h<<<EE*EE/1024, 256>>>(Wo, woh);
    cvt_h<<<4*EE*EE/1024, 256>>>(W1, w1h);
    cvt_h<<<4*EE*EE/1024, 256>>>(W2, w2h);

    // 1. QKV projections -> fp16 Q(*0.125)/K/V [B,H,T,64]
    gemm_fp16<0><<<dim3(8, 32, 3), 256, GSMEM>>>(
        xh, wqh, wkh, wvh, nullptr, nullptr, nullptr, nullptr, MTOT, 1024, 1024);
    // 2. causal attention -> fp16 O [B*T, E]
    attn_kernel<<<dim3(32, 16, 2), 128, ATTN_SMEM>>>(Ohp);
    // 3. out proj + bias + residual -> t1 (fp32)
    gemm_fp16<1><<<dim3(8, 32, 1), 256, GSMEM>>>(
        Ohp, woh, nullptr, nullptr, bo, x, t1, nullptr, MTOT, 1024, 1024);
    // 4. LN1 -> x1 (fp32) + x1h (fp16)
    ln_kernel<<<MTOT, 256>>>(t1, g1, be1, x1, x1h);
    // 5. FFN up + relu -> hh (fp16) [4096,4096]
    gemm_fp16<2><<<dim3(32, 32, 1), 256, GSMEM>>>(
        x1h, w1h, nullptr, nullptr, b1, nullptr, nullptr, hh, MTOT, 4096, 1024);
    // 6. FFN down + bias + residual -> t1 (fp32)
    gemm_fp16<1><<<dim3(8, 32, 1), 256, GSMEM>>>(
        hh, w2h, nullptr, nullptr, b2, x1, t1, nullptr, MTOT, 1024, 4096);
    // 7. LN2 -> output
    ln_kernel<<<MTOT, 256>>>(t1, g2, be2, out, nullptr);
}